// round 6
// baseline (speedup 1.0000x reference)
#include <cuda_runtime.h>
#include <cuda_bf16.h>
#include <math_constants.h>
#include <math.h>
#include <stdint.h>

#define B_N   8192
#define D_X   384
#define H_N   256
#define C_N   6
#define KMAX  16
#define NBLK  64
#define NPAIR (NBLK * (NBLK + 1) / 2)   // 2080
#define MTILE 128
#define NTILE 128
#define KPACK (2 * D_X)            // 768 stored ([hi|lo])
#define KSTEP 64
#define NKSTAGE 18                 // 3-term virtual K = 1152
#define STAGE_B 32768
#define KNN_SMEM (1024 + 3 * STAGE_B)  // 99328

// -------- device scratch --------
__device__ float g_sq[B_N];
__device__ int   g_k[B_N];
__device__ __align__(16) __nv_bfloat16 g_xp[(size_t)B_N * KPACK];
__device__ __align__(16) __nv_bfloat16 g_wp[(size_t)H_N * KPACK];
__device__ float g_h[(size_t)B_N * H_N];
__device__ unsigned long long g_pk [(size_t)NBLK * B_N * KMAX];  // slot-major packed lists, 67 MB
__device__ unsigned long long g_pk2[(size_t)8 * B_N * KMAX];     // group-major, 8.4 MB
__device__ int   g_idx[(size_t)B_N * KMAX];

typedef unsigned long long u64;

__device__ __forceinline__ u64 pack_key(float d, int j) {
    uint32_t k = __float_as_uint(d);
    k ^= (uint32_t)(((int)k >> 31)) | 0x80000000u;   // total-order map
    return ((u64)k << 32) | (uint32_t)j;
}

// virtual-K stage -> element offset in packed array
__device__ __forceinline__ int aOffE(int s) { return (s < 6 ? s : s - 6) * KSTEP; }
__device__ __forceinline__ int bOffE(int s) { return (s < 12 ? s : s - 12) * KSTEP; }

// ================= PTX helpers =================
__device__ __forceinline__ uint32_t smem_u32(const void* p) {
    uint32_t a;
    asm("{ .reg .u64 t; cvta.to.shared.u64 t, %1; cvt.u32.u64 %0, t; }" : "=r"(a) : "l"(p));
    return a;
}
#define CP_ASYNC16(s, g) asm volatile("cp.async.cg.shared.global [%0], [%1], 16;" :: "r"(s), "l"(g))
#define CP_COMMIT()      asm volatile("cp.async.commit_group;")
#define CP_WAIT1()       asm volatile("cp.async.wait_group 1;")
#define CP_WAIT0()       asm volatile("cp.async.wait_group 0;")

#define LDSM4(r0, r1, r2, r3, addr) \
    asm volatile("ldmatrix.sync.aligned.m8n8.x4.shared.b16 {%0,%1,%2,%3}, [%4];" \
        : "=r"(r0), "=r"(r1), "=r"(r2), "=r"(r3) : "r"(addr))

#define MMA16816(c, a, b0, b1) \
    asm volatile("mma.sync.aligned.m16n8k16.row.col.f32.bf16.bf16.f32 " \
        "{%0,%1,%2,%3}, {%4,%5,%6,%7}, {%8,%9}, {%0,%1,%2,%3};" \
        : "+f"((c)[0]), "+f"((c)[1]), "+f"((c)[2]), "+f"((c)[3]) \
        : "r"((a)[0]), "r"((a)[1]), "r"((a)[2]), "r"((a)[3]), "r"(b0), "r"(b1))

// ============================================================
// 0a) pack x -> [hi|lo] bf16
// ============================================================
__global__ void pack_kernel(const float* __restrict__ x) {
    int i = blockIdx.x * 256 + threadIdx.x;
    float4 v = ((const float4*)x)[i];
    int row = i / (D_X / 4);
    int c4  = (i % (D_X / 4)) * 4;
    float f[4] = {v.x, v.y, v.z, v.w};
    __nv_bfloat16 h[4], l[4];
    #pragma unroll
    for (int q = 0; q < 4; q++) {
        h[q] = __float2bfloat16(f[q]);
        l[q] = __float2bfloat16(f[q] - __bfloat162float(h[q]));
    }
    __nv_bfloat16* P = g_xp + (size_t)row * KPACK + c4;
    __nv_bfloat162 h0; h0.x = h[0]; h0.y = h[1];
    __nv_bfloat162 h1; h1.x = h[2]; h1.y = h[3];
    __nv_bfloat162 l0; l0.x = l[0]; l0.y = l[1];
    __nv_bfloat162 l1; l1.x = l[2]; l1.y = l[3];
    *(__nv_bfloat162*)(P)         = h0; *(__nv_bfloat162*)(P + 2)         = h1;
    *(__nv_bfloat162*)(P + D_X)   = l0; *(__nv_bfloat162*)(P + D_X + 2)   = l1;
}

// 0b) pack W_proj^T -> [hi|lo] bf16
__global__ void packw_kernel(const float* __restrict__ W) {
    int i = blockIdx.x * 256 + threadIdx.x;
    int k = i / H_N, n = i % H_N;
    float f = W[i];
    __nv_bfloat16 h = __float2bfloat16(f);
    __nv_bfloat16 l = __float2bfloat16(f - __bfloat162float(h));
    g_wp[(size_t)n * KPACK + k]       = h;
    g_wp[(size_t)n * KPACK + D_X + k] = l;
}

// ============================================================
// 1) prep: sq + adaptive k
// ============================================================
__global__ void prep_kernel(const float* __restrict__ x,
                            const float* __restrict__ W_tau,
                            const float* __restrict__ b_tau) {
    int row = blockIdx.x;
    const float* xr = x + (size_t)row * D_X;
    float s = 0.f, tt = 0.f;
    for (int i = threadIdx.x; i < D_X; i += 128) {
        float v = xr[i];
        s  = fmaf(v, v, s);
        tt = fmaf(v, W_tau[i], tt);
    }
    #pragma unroll
    for (int o = 16; o > 0; o >>= 1) {
        s  += __shfl_xor_sync(~0u, s, o);
        tt += __shfl_xor_sync(~0u, tt, o);
    }
    __shared__ float sh[8];
    int w = threadIdx.x >> 5, l = threadIdx.x & 31;
    if (l == 0) { sh[w] = s; sh[4 + w] = tt; }
    __syncthreads();
    if (threadIdx.x == 0) {
        float S = sh[0] + sh[1] + sh[2] + sh[3];
        float T = sh[4] + sh[5] + sh[6] + sh[7] + b_tau[0];
        g_sq[row] = S;
        float tau = 1.f / (1.f + expf(-T));
        float kf  = rintf(16.f - 12.f * tau);
        kf = fminf(fmaxf(kf, 1.f), 16.f);
        g_k[row] = (int)kf;
    }
}

// ============================================================
// shared 128x128 GEMM mainloop
// ============================================================
__device__ __forceinline__ void stage_load(uint32_t sbase,
                                           const __nv_bfloat16* gA,
                                           const __nv_bfloat16* gB, int tid) {
    #pragma unroll
    for (int it = 0; it < 8; it++) {
        int idx = tid + it * 128;
        int r = idx >> 3, c = idx & 7;
        uint32_t off = (uint32_t)(r * 128 + c * 16);
        off ^= (off >> 3) & 0x70;
        CP_ASYNC16(sbase + off,         (const char*)(gA + (size_t)r * KPACK) + c * 16);
        CP_ASYNC16(sbase + 16384 + off, (const char*)(gB + (size_t)r * KPACK) + c * 16);
    }
}

__device__ __forceinline__ void gemm_tile(uint32_t stage_base,
    const __nv_bfloat16* gA0, const __nv_bfloat16* gB0, int tid,
    const uint32_t arow_off[4], const uint32_t arow_x[4],
    const uint32_t brow_off[4], const uint32_t brow_x[4],
    uint32_t a_hi, uint32_t b_hi, float acc[4][8][4]) {

    #pragma unroll
    for (int i = 0; i < 4; i++)
        #pragma unroll
        for (int j = 0; j < 8; j++)
            #pragma unroll
            for (int q = 0; q < 4; q++) acc[i][j][q] = 0.f;

    stage_load(stage_base,           gA0 + aOffE(0), gB0 + bOffE(0), tid); CP_COMMIT();
    stage_load(stage_base + STAGE_B, gA0 + aOffE(1), gB0 + bOffE(1), tid); CP_COMMIT();

    for (int s = 0; s < NKSTAGE; s++) {
        if (s + 2 < NKSTAGE) { CP_WAIT1(); } else { CP_WAIT0(); }
        __syncthreads();
        if (s + 2 < NKSTAGE) {
            stage_load(stage_base + ((s + 2) % 3) * STAGE_B,
                       gA0 + aOffE(s + 2), gB0 + bOffE(s + 2), tid);
            CP_COMMIT();
        }
        uint32_t stA = stage_base + (s % 3) * STAGE_B;
        uint32_t stB = stA + 16384;
        #pragma unroll
        for (int kk = 0; kk < 4; kk++) {
            uint32_t a[4][4], b[4][4];
            #pragma unroll
            for (int i = 0; i < 4; i++) {
                uint32_t ck = (uint32_t)(2 * kk) + a_hi;
                uint32_t ad = stA + arow_off[i] + ((ck ^ arow_x[i]) << 4);
                LDSM4(a[i][0], a[i][1], a[i][2], a[i][3], ad);
            }
            #pragma unroll
            for (int p = 0; p < 4; p++) {
                uint32_t ck = (uint32_t)(2 * kk) + b_hi;
                uint32_t ad = stB + brow_off[p] + ((ck ^ brow_x[p]) << 4);
                LDSM4(b[p][0], b[p][1], b[p][2], b[p][3], ad);
            }
            #pragma unroll
            for (int i = 0; i < 4; i++)
                #pragma unroll
                for (int j = 0; j < 8; j++)
                    MMA16816(acc[i][j], a[i], b[j >> 1][(j & 1) * 2], b[j >> 1][(j & 1) * 2 + 1]);
        }
    }
}

// ============================================================
// 3) knn: one CTA per unordered block pair; dual-view packed top-16
// ============================================================
__global__ __launch_bounds__(128, 2) void knn_kernel() {
    extern __shared__ char smem[];
    uint32_t smem_base = smem_u32(smem);
    float* sqi = (float*)smem;
    float* sqj = (float*)(smem + 512);
    int tid = threadIdx.x, lane = tid & 31, warp = tid >> 5;
    int wm = warp >> 1, wn = warp & 1;

    // decode triangular pair (bi <= bj)
    int t = blockIdx.x;
    int bi = (int)((129.0f - sqrtf(16641.0f - 8.0f * (float)t)) * 0.5f);
    if (bi > NBLK - 1) bi = NBLK - 1;
    while (bi > 0 && t < bi * NBLK - bi * (bi - 1) / 2) bi--;
    while (t >= (bi + 1) * NBLK - (bi + 1) * bi / 2) bi++;
    int bj = bi + (t - (bi * NBLK - bi * (bi - 1) / 2));

    int rowBase = bi * MTILE;
    int colBase = bj * MTILE;

    sqi[tid] = g_sq[rowBase + tid];
    sqj[tid] = g_sq[colBase + tid];

    uint32_t a_hi = (uint32_t)((lane >> 4) & 1);
    uint32_t b_hi = (uint32_t)((lane >> 3) & 1);
    int aRow = wm * 64 + (lane & 15);
    int bRow = wn * 64 + (lane & 7) + (((lane >> 4) & 1) << 3);
    uint32_t arow_off[4], arow_x[4], brow_off[4], brow_x[4];
    #pragma unroll
    for (int i = 0; i < 4; i++) { int r = aRow + i * 16; arow_off[i] = r * 128; arow_x[i] = r & 7; }
    #pragma unroll
    for (int p = 0; p < 4; p++) { int r = bRow + p * 16; brow_off[p] = r * 128; brow_x[p] = r & 7; }

    float acc[4][8][4];
    gemm_tile(smem_base + 1024,
              g_xp + (size_t)rowBase * KPACK,
              g_xp + (size_t)colBase * KPACK, tid,
              arow_off, arow_x, brow_off, brow_x, a_hi, b_hi, acc);

    __syncthreads();
    float* sD = (float*)(smem + 1024);
    int r0l = wm * 64 + (lane >> 2);
    int c0l = wn * 64 + (lane & 3) * 2;
    #pragma unroll
    for (int i = 0; i < 4; i++) {
        int r = r0l + i * 16;
        #pragma unroll
        for (int j = 0; j < 8; j++) {
            int c = c0l + j * 8;
            sD[r * 129 + c]           = acc[i][j][0];
            sD[r * 129 + c + 1]       = acc[i][j][1];
            sD[(r + 8) * 129 + c]     = acc[i][j][2];
            sD[(r + 8) * 129 + c + 1] = acc[i][j][3];
        }
    }
    __syncthreads();

    u64 key[16];

    // row-side view: owner row = rowBase+tid, candidates = colBase + c
    #pragma unroll
    for (int p = 0; p < 16; p++) key[p] = ~0ull;
    #pragma unroll 4
    for (int c = 0; c < 128; c++) {
        float d = fmaf(-2.f, sD[tid * 129 + c], sqj[c]);
        u64 kk64 = pack_key(d, colBase + c);
        if (kk64 < key[15]) {
            u64 v = kk64;
            #pragma unroll
            for (int p = 0; p < 16; p++) {
                if (v < key[p]) { u64 tmp = key[p]; key[p] = v; v = tmp; }
            }
        }
    }
    {
        size_t base = ((size_t)bj * B_N + rowBase + tid) * KMAX;
        #pragma unroll
        for (int p = 0; p < 16; p++) g_pk[base + p] = key[p];
    }

    // col-side view (skip on diagonal)
    if (bi != bj) {
        #pragma unroll
        for (int p = 0; p < 16; p++) key[p] = ~0ull;
        #pragma unroll 4
        for (int r = 0; r < 128; r++) {
            float d = fmaf(-2.f, sD[r * 129 + tid], sqi[r]);
            u64 kk64 = pack_key(d, rowBase + r);
            if (kk64 < key[15]) {
                u64 v = kk64;
                #pragma unroll
                for (int p = 0; p < 16; p++) {
                    if (v < key[p]) { u64 tmp = key[p]; key[p] = v; v = tmp; }
                }
            }
        }
        size_t base = ((size_t)bi * B_N + colBase + tid) * KMAX;
        #pragma unroll
        for (int p = 0; p < 16; p++) g_pk[base + p] = key[p];
    }
}

// ============================================================
// 2) proj via mma
// ============================================================
__global__ __launch_bounds__(128, 2) void projmma_kernel(const float* __restrict__ b_proj) {
    extern __shared__ char smem[];
    uint32_t smem_base = smem_u32(smem);
    int tid = threadIdx.x, lane = tid & 31, warp = tid >> 5;
    int wm = warp >> 1, wn = warp & 1;

    int rowBase = blockIdx.x * MTILE;
    int colTile = blockIdx.y * NTILE;

    uint32_t a_hi = (uint32_t)((lane >> 4) & 1);
    uint32_t b_hi = (uint32_t)((lane >> 3) & 1);
    int aRow = wm * 64 + (lane & 15);
    int bRow = wn * 64 + (lane & 7) + (((lane >> 4) & 1) << 3);
    uint32_t arow_off[4], arow_x[4], brow_off[4], brow_x[4];
    #pragma unroll
    for (int i = 0; i < 4; i++) { int r = aRow + i * 16; arow_off[i] = r * 128; arow_x[i] = r & 7; }
    #pragma unroll
    for (int p = 0; p < 4; p++) { int r = bRow + p * 16; brow_off[p] = r * 128; brow_x[p] = r & 7; }

    float acc[4][8][4];
    gemm_tile(smem_base + 1024,
              g_xp + (size_t)rowBase * KPACK,
              g_wp + (size_t)colTile * KPACK, tid,
              arow_off, arow_x, brow_off, brow_x, a_hi, b_hi, acc);

    int r0l = rowBase + wm * 64 + (lane >> 2);
    int c0l = colTile + wn * 64 + (lane & 3) * 2;
    #pragma unroll
    for (int j = 0; j < 8; j++) {
        int c = c0l + j * 8;
        float bp0 = b_proj[c], bp1 = b_proj[c + 1];
        #pragma unroll
        for (int i = 0; i < 4; i++) {
            int r = r0l + i * 16;
            g_h[(size_t)r * H_N + c]           = fmaxf(acc[i][j][0] + bp0, 0.f);
            g_h[(size_t)r * H_N + c + 1]       = fmaxf(acc[i][j][1] + bp1, 0.f);
            g_h[(size_t)(r + 8) * H_N + c]     = fmaxf(acc[i][j][2] + bp0, 0.f);
            g_h[(size_t)(r + 8) * H_N + c + 1] = fmaxf(acc[i][j][3] + bp1, 0.f);
        }
    }
}

// ============================================================
// 4) two-level merge of 64 sorted packed lists per row (coalesced)
// ============================================================
__global__ void merge1_kernel() {
    int id = blockIdx.x * 256 + threadIdx.x;       // B_N*8 total
    int g = id >> 13, row = id & (B_N - 1);        // row fastest -> coalesced
    u64 key[16];
    #pragma unroll
    for (int p = 0; p < 16; p++) key[p] = ~0ull;
    for (int s = 0; s < 8; s++) {
        size_t base = ((size_t)(g * 8 + s) * B_N + row) * KMAX;
        for (int q = 0; q < 16; q++) {
            u64 v = g_pk[base + q];
            if (v >= key[15]) break;                 // sorted list: rest can't enter
            u64 vv = v;
            #pragma unroll
            for (int p = 0; p < 16; p++) {
                if (vv < key[p]) { u64 tmp = key[p]; key[p] = vv; vv = tmp; }
            }
        }
    }
    size_t ob = ((size_t)g * B_N + row) * KMAX;
    #pragma unroll
    for (int p = 0; p < 16; p++) g_pk2[ob + p] = key[p];
}

__global__ void merge2_kernel() {
    int row = blockIdx.x * 128 + threadIdx.x;
    u64 key[16];
    #pragma unroll
    for (int p = 0; p < 16; p++) key[p] = ~0ull;
    for (int s = 0; s < 8; s++) {
        size_t base = ((size_t)s * B_N + row) * KMAX;
        for (int q = 0; q < 16; q++) {
            u64 v = g_pk2[base + q];
            if (v >= key[15]) break;
            u64 vv = v;
            #pragma unroll
            for (int p = 0; p < 16; p++) {
                if (vv < key[p]) { u64 tmp = key[p]; key[p] = vv; vv = tmp; }
            }
        }
    }
    #pragma unroll
    for (int p = 0; p < 16; p++) g_idx[(size_t)row * KMAX + p] = (int)(key[p] & 0xFFFFFFFFull);
}

// ============================================================
// 5) fused: agg gather + residual + LayerNorm + fc
// ============================================================
__global__ __launch_bounds__(256) void resln_kernel(const float* __restrict__ W_res,
                                                    const float* __restrict__ b_res,
                                                    const float* __restrict__ ln_g,
                                                    const float* __restrict__ ln_b,
                                                    const float* __restrict__ W_fc,
                                                    const float* __restrict__ b_fc,
                                                    float* __restrict__ out) {
    __shared__ float sAgg[16][256];
    __shared__ float sZ[16][256];
    __shared__ float sG[256], sBn[256], sWfc[256 * 6], sbfc[6];
    __shared__ int sidx[16][16];
    __shared__ int sK[16];
    __shared__ float sKi[16];
    int j = threadIdx.x;
    int r0 = blockIdx.x * 16;

    { int rr = j >> 4, q = j & 15; sidx[rr][q] = g_idx[(size_t)(r0 + rr) * KMAX + q]; }
    if (j < 16) { int k = g_k[r0 + j]; sK[j] = k; sKi[j] = 1.f / (float)k; }
    sG[j] = ln_g[j]; sBn[j] = ln_b[j];
    for (int l = j; l < 256 * 6; l += 256) sWfc[l] = W_fc[l];
    if (j < 6) sbfc[j] = b_fc[j];
    float br = b_res[j];
    __syncthreads();

    for (int r = 0; r < 16; r++) {
        int k = sK[r];
        float s = 0.f;
        for (int t = 0; t < k; t++) s += g_h[(size_t)sidx[r][t] * H_N + j];
        sAgg[r][j] = s * sKi[r];
    }
    __syncthreads();

    float acc[16];
    #pragma unroll
    for (int r = 0; r < 16; r++) acc[r] = 0.f;
    for (int t = 0; t < 256; t++) {
        float w = W_res[(size_t)t * H_N + j];
        #pragma unroll
        for (int r = 0; r < 16; r++) acc[r] = fmaf(sAgg[r][t], w, acc[r]);
    }
    #pragma unroll
    for (int r = 0; r < 16; r++) {
        float rv = fmaxf(acc[r] + br, 0.f);
        sZ[r][j] = g_h[(size_t)(r0 + r) * H_N + j] + rv;
    }
    __syncthreads();

    int wid = j >> 5, lane = j & 31;
    for (int rr = 0; rr < 2; rr++) {
        int lr = wid * 2 + rr;
        int row = r0 + lr;
        float zv[8]; float s = 0.f, s2 = 0.f;
        #pragma unroll
        for (int q = 0; q < 8; q++) {
            zv[q] = sZ[lr][lane + q * 32];
            s += zv[q]; s2 = fmaf(zv[q], zv[q], s2);
        }
        #pragma unroll
        for (int o = 16; o > 0; o >>= 1) {
            s  += __shfl_xor_sync(~0u, s,  o);
            s2 += __shfl_xor_sync(~0u, s2, o);
        }
        float mu   = s * (1.f / 256.f);
        float var  = s2 * (1.f / 256.f) - mu * mu;
        float rstd = 1.0f / sqrtf(var + 1e-5f);
        float po[6] = {0, 0, 0, 0, 0, 0};
        #pragma unroll
        for (int q = 0; q < 8; q++) {
            int tcol = lane + q * 32;
            float a = (zv[q] - mu) * rstd * sG[tcol] + sBn[tcol];
            #pragma unroll
            for (int c = 0; c < 6; c++) po[c] = fmaf(a, sWfc[tcol * 6 + c], po[c]);
        }
        #pragma unroll
        for (int c = 0; c < 6; c++) {
            #pragma unroll
            for (int o = 16; o > 0; o >>= 1) po[c] += __shfl_xor_sync(~0u, po[c], o);
        }
        if (lane == 0) {
            #pragma unroll
            for (int c = 0; c < 6; c++) out[(size_t)row * C_N + c] = po[c] + sbfc[c];
        }
    }
}

// ============================================================
extern "C" void kernel_launch(void* const* d_in, const int* in_sizes, int n_in,
                              void* d_out, int out_size) {
    const float* x      = (const float*)d_in[0];
    const float* W_proj = (const float*)d_in[1];
    const float* b_proj = (const float*)d_in[2];
    const float* W_tau  = (const float*)d_in[3];
    const float* b_tau  = (const float*)d_in[4];
    const float* W_res  = (const float*)d_in[5];
    const float* b_res  = (const float*)d_in[6];
    const float* ln_g   = (const float*)d_in[7];
    const float* ln_b   = (const float*)d_in[8];
    const float* W_fc   = (const float*)d_in[9];
    const float* b_fc   = (const float*)d_in[10];
    float* out = (float*)d_out;

    cudaFuncSetAttribute(knn_kernel,     cudaFuncAttributeMaxDynamicSharedMemorySize, KNN_SMEM);
    cudaFuncSetAttribute(projmma_kernel, cudaFuncAttributeMaxDynamicSharedMemorySize, KNN_SMEM);

    prep_kernel<<<B_N, 128>>>(x, W_tau, b_tau);
    pack_kernel<<<(B_N * D_X / 4) / 256, 256>>>(x);
    packw_kernel<<<(D_X * H_N) / 256, 256>>>(W_proj);
    projmma_kernel<<<dim3(B_N / MTILE, H_N / NTILE), 128, KNN_SMEM>>>(b_proj);
    knn_kernel<<<NPAIR, 128, KNN_SMEM>>>();
    merge1_kernel<<<B_N * 8 / 256, 256>>>();
    merge2_kernel<<<B_N / 128, 128>>>();
    resln_kernel<<<B_N / 16, 256>>>(W_res, b_res, ln_g, ln_b, W_fc, b_fc, out);
}

// round 9
// speedup vs baseline: 1.0215x; 1.0215x over previous
#include <cuda_runtime.h>
#include <cuda_bf16.h>
#include <math_constants.h>
#include <math.h>
#include <stdint.h>

#define B_N   8192
#define D_X   384
#define H_N   256
#define C_N   6
#define KMAX  16
#define NBLK  64
#define NPAIR (NBLK * (NBLK + 1) / 2)   // 2080
#define MTILE 128
#define NTILE 128
#define KPACK (2 * D_X)            // 768 stored ([hi|lo])
#define KSTEP 64
#define NKSTAGE 18                 // 3-term virtual K = 1152
#define STAGE_B 32768
#define KNN_SMEM (1024 + 3 * STAGE_B)  // 99328

// -------- device scratch --------
__device__ float g_sq[B_N];
__device__ int   g_k[B_N];
__device__ __align__(16) __nv_bfloat16 g_xp[(size_t)B_N * KPACK];
__device__ __align__(16) __nv_bfloat16 g_wp[(size_t)H_N * KPACK];
__device__ float g_h[(size_t)B_N * H_N];
__device__ __align__(128) unsigned long long g_pk [(size_t)NBLK * B_N * KMAX];  // 67 MB
__device__ __align__(128) unsigned long long g_pk2[(size_t)8 * B_N * KMAX];     // 8.4 MB
__device__ int   g_idx[(size_t)B_N * KMAX];

typedef unsigned long long u64;

__device__ __forceinline__ u64 pack_key(float d, int j) {
    uint32_t k = __float_as_uint(d);
    k ^= (uint32_t)(((int)k >> 31)) | 0x80000000u;   // total-order map
    return ((u64)k << 32) | (uint32_t)j;
}

// virtual-K stage -> element offset in packed array
__device__ __forceinline__ int aOffE(int s) { return (s < 6 ? s : s - 6) * KSTEP; }
__device__ __forceinline__ int bOffE(int s) { return (s < 12 ? s : s - 12) * KSTEP; }

// ================= PTX helpers =================
__device__ __forceinline__ uint32_t smem_u32(const void* p) {
    uint32_t a;
    asm("{ .reg .u64 t; cvta.to.shared.u64 t, %1; cvt.u32.u64 %0, t; }" : "=r"(a) : "l"(p));
    return a;
}
#define CP_ASYNC16(s, g) asm volatile("cp.async.cg.shared.global [%0], [%1], 16;" :: "r"(s), "l"(g))
#define CP_COMMIT()      asm volatile("cp.async.commit_group;")
#define CP_WAIT1()       asm volatile("cp.async.wait_group 1;")
#define CP_WAIT0()       asm volatile("cp.async.wait_group 0;")

#define LDSM4(r0, r1, r2, r3, addr) \
    asm volatile("ldmatrix.sync.aligned.m8n8.x4.shared.b16 {%0,%1,%2,%3}, [%4];" \
        : "=r"(r0), "=r"(r1), "=r"(r2), "=r"(r3) : "r"(addr))

#define MMA16816(c, a, b0, b1) \
    asm volatile("mma.sync.aligned.m16n8k16.row.col.f32.bf16.bf16.f32 " \
        "{%0,%1,%2,%3}, {%4,%5,%6,%7}, {%8,%9}, {%0,%1,%2,%3};" \
        : "+f"((c)[0]), "+f"((c)[1]), "+f"((c)[2]), "+f"((c)[3]) \
        : "r"((a)[0]), "r"((a)[1]), "r"((a)[2]), "r"((a)[3]), "r"(b0), "r"(b1))

// ============================================================
// 0a) pack x -> [hi|lo] bf16
// ============================================================
__global__ void pack_kernel(const float* __restrict__ x) {
    int i = blockIdx.x * 256 + threadIdx.x;
    float4 v = ((const float4*)x)[i];
    int row = i / (D_X / 4);
    int c4  = (i % (D_X / 4)) * 4;
    float f[4] = {v.x, v.y, v.z, v.w};
    __nv_bfloat16 h[4], l[4];
    #pragma unroll
    for (int q = 0; q < 4; q++) {
        h[q] = __float2bfloat16(f[q]);
        l[q] = __float2bfloat16(f[q] - __bfloat162float(h[q]));
    }
    __nv_bfloat16* P = g_xp + (size_t)row * KPACK + c4;
    __nv_bfloat162 h0; h0.x = h[0]; h0.y = h[1];
    __nv_bfloat162 h1; h1.x = h[2]; h1.y = h[3];
    __nv_bfloat162 l0; l0.x = l[0]; l0.y = l[1];
    __nv_bfloat162 l1; l1.x = l[2]; l1.y = l[3];
    *(__nv_bfloat162*)(P)         = h0; *(__nv_bfloat162*)(P + 2)         = h1;
    *(__nv_bfloat162*)(P + D_X)   = l0; *(__nv_bfloat162*)(P + D_X + 2)   = l1;
}

// 0b) pack W_proj^T -> [hi|lo] bf16
__global__ void packw_kernel(const float* __restrict__ W) {
    int i = blockIdx.x * 256 + threadIdx.x;
    int k = i / H_N, n = i % H_N;
    float f = W[i];
    __nv_bfloat16 h = __float2bfloat16(f);
    __nv_bfloat16 l = __float2bfloat16(f - __bfloat162float(h));
    g_wp[(size_t)n * KPACK + k]       = h;
    g_wp[(size_t)n * KPACK + D_X + k] = l;
}

// ============================================================
// 1) prep: sq + adaptive k
// ============================================================
__global__ void prep_kernel(const float* __restrict__ x,
                            const float* __restrict__ W_tau,
                            const float* __restrict__ b_tau) {
    int row = blockIdx.x;
    const float* xr = x + (size_t)row * D_X;
    float s = 0.f, tt = 0.f;
    for (int i = threadIdx.x; i < D_X; i += 128) {
        float v = xr[i];
        s  = fmaf(v, v, s);
        tt = fmaf(v, W_tau[i], tt);
    }
    #pragma unroll
    for (int o = 16; o > 0; o >>= 1) {
        s  += __shfl_xor_sync(~0u, s, o);
        tt += __shfl_xor_sync(~0u, tt, o);
    }
    __shared__ float sh[8];
    int w = threadIdx.x >> 5, l = threadIdx.x & 31;
    if (l == 0) { sh[w] = s; sh[4 + w] = tt; }
    __syncthreads();
    if (threadIdx.x == 0) {
        float S = sh[0] + sh[1] + sh[2] + sh[3];
        float T = sh[4] + sh[5] + sh[6] + sh[7] + b_tau[0];
        g_sq[row] = S;
        float tau = 1.f / (1.f + expf(-T));
        float kf  = rintf(16.f - 12.f * tau);
        kf = fminf(fmaxf(kf, 1.f), 16.f);
        g_k[row] = (int)kf;
    }
}

// ============================================================
// shared 128x128 GEMM mainloop
// ============================================================
__device__ __forceinline__ void stage_load(uint32_t sbase,
                                           const __nv_bfloat16* gA,
                                           const __nv_bfloat16* gB, int tid) {
    #pragma unroll
    for (int it = 0; it < 8; it++) {
        int idx = tid + it * 128;
        int r = idx >> 3, c = idx & 7;
        uint32_t off = (uint32_t)(r * 128 + c * 16);
        off ^= (off >> 3) & 0x70;
        CP_ASYNC16(sbase + off,         (const char*)(gA + (size_t)r * KPACK) + c * 16);
        CP_ASYNC16(sbase + 16384 + off, (const char*)(gB + (size_t)r * KPACK) + c * 16);
    }
}

__device__ __forceinline__ void gemm_tile(uint32_t stage_base,
    const __nv_bfloat16* gA0, const __nv_bfloat16* gB0, int tid,
    const uint32_t arow_off[4], const uint32_t arow_x[4],
    const uint32_t brow_off[4], const uint32_t brow_x[4],
    uint32_t a_hi, uint32_t b_hi, float acc[4][8][4]) {

    #pragma unroll
    for (int i = 0; i < 4; i++)
        #pragma unroll
        for (int j = 0; j < 8; j++)
            #pragma unroll
            for (int q = 0; q < 4; q++) acc[i][j][q] = 0.f;

    stage_load(stage_base,           gA0 + aOffE(0), gB0 + bOffE(0), tid); CP_COMMIT();
    stage_load(stage_base + STAGE_B, gA0 + aOffE(1), gB0 + bOffE(1), tid); CP_COMMIT();

    for (int s = 0; s < NKSTAGE; s++) {
        if (s + 2 < NKSTAGE) { CP_WAIT1(); } else { CP_WAIT0(); }
        __syncthreads();
        if (s + 2 < NKSTAGE) {
            stage_load(stage_base + ((s + 2) % 3) * STAGE_B,
                       gA0 + aOffE(s + 2), gB0 + bOffE(s + 2), tid);
            CP_COMMIT();
        }
        uint32_t stA = stage_base + (s % 3) * STAGE_B;
        uint32_t stB = stA + 16384;
        #pragma unroll
        for (int kk = 0; kk < 4; kk++) {
            uint32_t a[4][4], b[4][4];
            #pragma unroll
            for (int i = 0; i < 4; i++) {
                uint32_t ck = (uint32_t)(2 * kk) + a_hi;
                uint32_t ad = stA + arow_off[i] + ((ck ^ arow_x[i]) << 4);
                LDSM4(a[i][0], a[i][1], a[i][2], a[i][3], ad);
            }
            #pragma unroll
            for (int p = 0; p < 4; p++) {
                uint32_t ck = (uint32_t)(2 * kk) + b_hi;
                uint32_t ad = stB + brow_off[p] + ((ck ^ brow_x[p]) << 4);
                LDSM4(b[p][0], b[p][1], b[p][2], b[p][3], ad);
            }
            #pragma unroll
            for (int i = 0; i < 4; i++)
                #pragma unroll
                for (int j = 0; j < 8; j++)
                    MMA16816(acc[i][j], a[i], b[j >> 1][(j & 1) * 2], b[j >> 1][(j & 1) * 2 + 1]);
        }
    }
}

// ============================================================
// 3) knn: one CTA per unordered block pair; dual-view packed top-16
// ============================================================
__global__ __launch_bounds__(128, 2) void knn_kernel() {
    extern __shared__ char smem[];
    uint32_t smem_base = smem_u32(smem);
    float* sqi = (float*)smem;
    float* sqj = (float*)(smem + 512);
    int tid = threadIdx.x, lane = tid & 31, warp = tid >> 5;
    int wm = warp >> 1, wn = warp & 1;

    // decode triangular pair (bi <= bj)
    int t = blockIdx.x;
    int bi = (int)((129.0f - sqrtf(16641.0f - 8.0f * (float)t)) * 0.5f);
    if (bi > NBLK - 1) bi = NBLK - 1;
    while (bi > 0 && t < bi * NBLK - bi * (bi - 1) / 2) bi--;
    while (t >= (bi + 1) * NBLK - (bi + 1) * bi / 2) bi++;
    int bj = bi + (t - (bi * NBLK - bi * (bi - 1) / 2));

    int rowBase = bi * MTILE;
    int colBase = bj * MTILE;

    sqi[tid] = g_sq[rowBase + tid];
    sqj[tid] = g_sq[colBase + tid];

    uint32_t a_hi = (uint32_t)((lane >> 4) & 1);
    uint32_t b_hi = (uint32_t)((lane >> 3) & 1);
    int aRow = wm * 64 + (lane & 15);
    int bRow = wn * 64 + (lane & 7) + (((lane >> 4) & 1) << 3);
    uint32_t arow_off[4], arow_x[4], brow_off[4], brow_x[4];
    #pragma unroll
    for (int i = 0; i < 4; i++) { int r = aRow + i * 16; arow_off[i] = r * 128; arow_x[i] = r & 7; }
    #pragma unroll
    for (int p = 0; p < 4; p++) { int r = bRow + p * 16; brow_off[p] = r * 128; brow_x[p] = r & 7; }

    float acc[4][8][4];
    gemm_tile(smem_base + 1024,
              g_xp + (size_t)rowBase * KPACK,
              g_xp + (size_t)colBase * KPACK, tid,
              arow_off, arow_x, brow_off, brow_x, a_hi, b_hi, acc);

    __syncthreads();
    float* sD = (float*)(smem + 1024);
    int r0l = wm * 64 + (lane >> 2);
    int c0l = wn * 64 + (lane & 3) * 2;
    #pragma unroll
    for (int i = 0; i < 4; i++) {
        int r = r0l + i * 16;
        #pragma unroll
        for (int j = 0; j < 8; j++) {
            int c = c0l + j * 8;
            sD[r * 129 + c]           = acc[i][j][0];
            sD[r * 129 + c + 1]       = acc[i][j][1];
            sD[(r + 8) * 129 + c]     = acc[i][j][2];
            sD[(r + 8) * 129 + c + 1] = acc[i][j][3];
        }
    }
    __syncthreads();

    u64 key[16];

    // row-side view: owner row = rowBase+tid, candidates = colBase + c
    #pragma unroll
    for (int p = 0; p < 16; p++) key[p] = ~0ull;
    #pragma unroll 4
    for (int c = 0; c < 128; c++) {
        float d = fmaf(-2.f, sD[tid * 129 + c], sqj[c]);
        u64 kk64 = pack_key(d, colBase + c);
        if (kk64 < key[15]) {
            u64 v = kk64;
            #pragma unroll
            for (int p = 0; p < 16; p++) {
                if (v < key[p]) { u64 tmp = key[p]; key[p] = v; v = tmp; }
            }
        }
    }
    {
        size_t base = ((size_t)bj * B_N + rowBase + tid) * KMAX;
        #pragma unroll
        for (int p = 0; p < 16; p++) g_pk[base + p] = key[p];
    }

    // col-side view (skip on diagonal)
    if (bi != bj) {
        #pragma unroll
        for (int p = 0; p < 16; p++) key[p] = ~0ull;
        #pragma unroll 4
        for (int r = 0; r < 128; r++) {
            float d = fmaf(-2.f, sD[r * 129 + tid], sqi[r]);
            u64 kk64 = pack_key(d, rowBase + r);
            if (kk64 < key[15]) {
                u64 v = kk64;
                #pragma unroll
                for (int p = 0; p < 16; p++) {
                    if (v < key[p]) { u64 tmp = key[p]; key[p] = v; v = tmp; }
                }
            }
        }
        size_t base = ((size_t)bi * B_N + colBase + tid) * KMAX;
        #pragma unroll
        for (int p = 0; p < 16; p++) g_pk[base + p] = key[p];
    }
}

// ============================================================
// 2) proj via mma
// ============================================================
__global__ __launch_bounds__(128, 2) void projmma_kernel(const float* __restrict__ b_proj) {
    extern __shared__ char smem[];
    uint32_t smem_base = smem_u32(smem);
    int tid = threadIdx.x, lane = tid & 31, warp = tid >> 5;
    int wm = warp >> 1, wn = warp & 1;

    int rowBase = blockIdx.x * MTILE;
    int colTile = blockIdx.y * NTILE;

    uint32_t a_hi = (uint32_t)((lane >> 4) & 1);
    uint32_t b_hi = (uint32_t)((lane >> 3) & 1);
    int aRow = wm * 64 + (lane & 15);
    int bRow = wn * 64 + (lane & 7) + (((lane >> 4) & 1) << 3);
    uint32_t arow_off[4], arow_x[4], brow_off[4], brow_x[4];
    #pragma unroll
    for (int i = 0; i < 4; i++) { int r = aRow + i * 16; arow_off[i] = r * 128; arow_x[i] = r & 7; }
    #pragma unroll
    for (int p = 0; p < 4; p++) { int r = bRow + p * 16; brow_off[p] = r * 128; brow_x[p] = r & 7; }

    float acc[4][8][4];
    gemm_tile(smem_base + 1024,
              g_xp + (size_t)rowBase * KPACK,
              g_wp + (size_t)colTile * KPACK, tid,
              arow_off, arow_x, brow_off, brow_x, a_hi, b_hi, acc);

    int r0l = rowBase + wm * 64 + (lane >> 2);
    int c0l = colTile + wn * 64 + (lane & 3) * 2;
    #pragma unroll
    for (int j = 0; j < 8; j++) {
        int c = c0l + j * 8;
        float bp0 = b_proj[c], bp1 = b_proj[c + 1];
        #pragma unroll
        for (int i = 0; i < 4; i++) {
            int r = r0l + i * 16;
            g_h[(size_t)r * H_N + c]           = fmaxf(acc[i][j][0] + bp0, 0.f);
            g_h[(size_t)r * H_N + c + 1]       = fmaxf(acc[i][j][1] + bp1, 0.f);
            g_h[(size_t)(r + 8) * H_N + c]     = fmaxf(acc[i][j][2] + bp0, 0.f);
            g_h[(size_t)(r + 8) * H_N + c + 1] = fmaxf(acc[i][j][3] + bp1, 0.f);
        }
    }
}

// ============================================================
// 4) two-level merge, vectorized: each list = one 128-B line,
//    loaded as 8 independent ulonglong2 (MLP=8), insert in regs.
// ============================================================
__global__ void merge1_kernel() {
    int id = blockIdx.x * 256 + threadIdx.x;       // B_N*8 total
    int g = id >> 13, row = id & (B_N - 1);
    u64 key[16];
    #pragma unroll
    for (int p = 0; p < 16; p++) key[p] = ~0ull;
    for (int s = 0; s < 8; s++) {
        const u64* L = g_pk + ((size_t)(g * 8 + s) * B_N + row) * KMAX;
        ulonglong2 v[8];
        #pragma unroll
        for (int q = 0; q < 8; q++) v[q] = *(const ulonglong2*)(L + q * 2);
        #pragma unroll
        for (int q = 0; q < 8; q++) {
            u64 a = v[q].x;
            if (a >= key[15]) break;
            #pragma unroll
            for (int p = 0; p < 16; p++)
                if (a < key[p]) { u64 tmp = key[p]; key[p] = a; a = tmp; }
            u64 b = v[q].y;
            if (b >= key[15]) break;
            #pragma unroll
            for (int p = 0; p < 16; p++)
                if (b < key[p]) { u64 tmp = key[p]; key[p] = b; b = tmp; }
        }
    }
    size_t ob = ((size_t)g * B_N + row) * KMAX;
    #pragma unroll
    for (int p = 0; p < 16; p++) g_pk2[ob + p] = key[p];
}

__global__ void merge2_kernel() {
    int row = blockIdx.x * 128 + threadIdx.x;
    u64 key[16];
    #pragma unroll
    for (int p = 0; p < 16; p++) key[p] = ~0ull;
    for (int s = 0; s < 8; s++) {
        const u64* L = g_pk2 + ((size_t)s * B_N + row) * KMAX;
        ulonglong2 v[8];
        #pragma unroll
        for (int q = 0; q < 8; q++) v[q] = *(const ulonglong2*)(L + q * 2);
        #pragma unroll
        for (int q = 0; q < 8; q++) {
            u64 a = v[q].x;
            if (a >= key[15]) break;
            #pragma unroll
            for (int p = 0; p < 16; p++)
                if (a < key[p]) { u64 tmp = key[p]; key[p] = a; a = tmp; }
            u64 b = v[q].y;
            if (b >= key[15]) break;
            #pragma unroll
            for (int p = 0; p < 16; p++)
                if (b < key[p]) { u64 tmp = key[p]; key[p] = b; b = tmp; }
        }
    }
    #pragma unroll
    for (int p = 0; p < 16; p++) g_idx[(size_t)row * KMAX + p] = (int)(key[p] & 0xFFFFFFFFull);
}

// ============================================================
// 5) fused: agg gather + residual + LayerNorm + fc
// ============================================================
__global__ __launch_bounds__(256) void resln_kernel(const float* __restrict__ W_res,
                                                    const float* __restrict__ b_res,
                                                    const float* __restrict__ ln_g,
                                                    const float* __restrict__ ln_b,
                                                    const float* __restrict__ W_fc,
                                                    const float* __restrict__ b_fc,
                                                    float* __restrict__ out) {
    __shared__ float sAgg[16][256];
    __shared__ float sZ[16][256];
    __shared__ float sG[256], sBn[256], sWfc[256 * 6], sbfc[6];
    __shared__ int sidx[16][16];
    __shared__ int sK[16];
    __shared__ float sKi[16];
    int j = threadIdx.x;
    int r0 = blockIdx.x * 16;

    { int rr = j >> 4, q = j & 15; sidx[rr][q] = g_idx[(size_t)(r0 + rr) * KMAX + q]; }
    if (j < 16) { int k = g_k[r0 + j]; sK[j] = k; sKi[j] = 1.f / (float)k; }
    sG[j] = ln_g[j]; sBn[j] = ln_b[j];
    for (int l = j; l < 256 * 6; l += 256) sWfc[l] = W_fc[l];
    if (j < 6) sbfc[j] = b_fc[j];
    float br = b_res[j];
    __syncthreads();

    for (int r = 0; r < 16; r++) {
        int k = sK[r];
        float s = 0.f;
        for (int t = 0; t < k; t++) s += g_h[(size_t)sidx[r][t] * H_N + j];
        sAgg[r][j] = s * sKi[r];
    }
    __syncthreads();

    float acc[16];
    #pragma unroll
    for (int r = 0; r < 16; r++) acc[r] = 0.f;
    for (int t = 0; t < 256; t++) {
        float w = W_res[(size_t)t * H_N + j];
        #pragma unroll
        for (int r = 0; r < 16; r++) acc[r] = fmaf(sAgg[r][t], w, acc[r]);
    }
    #pragma unroll
    for (int r = 0; r < 16; r++) {
        float rv = fmaxf(acc[r] + br, 0.f);
        sZ[r][j] = g_h[(size_t)(r0 + r) * H_N + j] + rv;
    }
    __syncthreads();

    int wid = j >> 5, lane = j & 31;
    for (int rr = 0; rr < 2; rr++) {
        int lr = wid * 2 + rr;
        int row = r0 + lr;
        float zv[8]; float s = 0.f, s2 = 0.f;
        #pragma unroll
        for (int q = 0; q < 8; q++) {
            zv[q] = sZ[lr][lane + q * 32];
            s += zv[q]; s2 = fmaf(zv[q], zv[q], s2);
        }
        #pragma unroll
        for (int o = 16; o > 0; o >>= 1) {
            s  += __shfl_xor_sync(~0u, s,  o);
            s2 += __shfl_xor_sync(~0u, s2, o);
        }
        float mu   = s * (1.f / 256.f);
        float var  = s2 * (1.f / 256.f) - mu * mu;
        float rstd = 1.0f / sqrtf(var + 1e-5f);
        float po[6] = {0, 0, 0, 0, 0, 0};
        #pragma unroll
        for (int q = 0; q < 8; q++) {
            int tcol = lane + q * 32;
            float a = (zv[q] - mu) * rstd * sG[tcol] + sBn[tcol];
            #pragma unroll
            for (int c = 0; c < 6; c++) po[c] = fmaf(a, sWfc[tcol * 6 + c], po[c]);
        }
        #pragma unroll
        for (int c = 0; c < 6; c++) {
            #pragma unroll
            for (int o = 16; o > 0; o >>= 1) po[c] += __shfl_xor_sync(~0u, po[c], o);
        }
        if (lane == 0) {
            #pragma unroll
            for (int c = 0; c < 6; c++) out[(size_t)row * C_N + c] = po[c] + sbfc[c];
        }
    }
}

// ============================================================
extern "C" void kernel_launch(void* const* d_in, const int* in_sizes, int n_in,
                              void* d_out, int out_size) {
    const float* x      = (const float*)d_in[0];
    const float* W_proj = (const float*)d_in[1];
    const float* b_proj = (const float*)d_in[2];
    const float* W_tau  = (const float*)d_in[3];
    const float* b_tau  = (const float*)d_in[4];
    const float* W_res  = (const float*)d_in[5];
    const float* b_res  = (const float*)d_in[6];
    const float* ln_g   = (const float*)d_in[7];
    const float* ln_b   = (const float*)d_in[8];
    const float* W_fc   = (const float*)d_in[9];
    const float* b_fc   = (const float*)d_in[10];
    float* out = (float*)d_out;

    cudaFuncSetAttribute(knn_kernel,     cudaFuncAttributeMaxDynamicSharedMemorySize, KNN_SMEM);
    cudaFuncSetAttribute(projmma_kernel, cudaFuncAttributeMaxDynamicSharedMemorySize, KNN_SMEM);

    prep_kernel<<<B_N, 128>>>(x, W_tau, b_tau);
    pack_kernel<<<(B_N * D_X / 4) / 256, 256>>>(x);
    packw_kernel<<<(D_X * H_N) / 256, 256>>>(W_proj);
    projmma_kernel<<<dim3(B_N / MTILE, H_N / NTILE), 128, KNN_SMEM>>>(b_proj);
    knn_kernel<<<NPAIR, 128, KNN_SMEM>>>();
    merge1_kernel<<<B_N * 8 / 256, 256>>>();
    merge2_kernel<<<B_N / 128, 128>>>();
    resln_kernel<<<B_N / 16, 256>>>(W_res, b_res, ln_g, ln_b, W_fc, b_fc, out);
}

// round 10
// speedup vs baseline: 1.4918x; 1.4604x over previous
#include <cuda_runtime.h>
#include <cuda_bf16.h>
#include <math_constants.h>
#include <math.h>
#include <stdint.h>

#define B_N   8192
#define D_X   384
#define H_N   256
#define C_N   6
#define KMAX  16
#define JSPLIT 32
#define JCHUNK (B_N / JSPLIT)      // 256
#define MTILE 128
#define NTILE 128
#define NT_PER (JCHUNK / NTILE)    // 2
#define KPACK (2 * D_X)            // 768 stored ([hi|lo])
#define KSTEP 64
#define NKSTAGE 18                 // 3-term virtual K = 1152
#define STAGE_B 32768
#define KNN_SMEM (1024 + 3 * STAGE_B)  // 99328

// -------- device scratch --------
__device__ float g_sq[B_N];
__device__ int   g_k[B_N];
__device__ __align__(16) __nv_bfloat16 g_xp[(size_t)B_N * KPACK];
__device__ __align__(16) __nv_bfloat16 g_wp[(size_t)H_N * KPACK];
__device__ float g_h[(size_t)B_N * H_N];
__device__ __align__(128) unsigned long long g_pk[(size_t)JSPLIT * B_N * KMAX];  // 33.5 MB
__device__ int   g_idx[(size_t)B_N * KMAX];

typedef unsigned long long u64;

__device__ __forceinline__ u64 pack_key(float d, int j) {
    uint32_t k = __float_as_uint(d);
    k ^= (uint32_t)(((int)k >> 31)) | 0x80000000u;   // total-order map
    return ((u64)k << 32) | (uint32_t)j;
}

// virtual-K stage -> element offset in packed array
__device__ __forceinline__ int aOffE(int s) { return (s < 6 ? s : s - 6) * KSTEP; }   // [hi|hi|lo]
__device__ __forceinline__ int bOffE(int s) { return (s < 12 ? s : s - 12) * KSTEP; } // [hi|lo|hi]

// ================= PTX helpers =================
__device__ __forceinline__ uint32_t smem_u32(const void* p) {
    uint32_t a;
    asm("{ .reg .u64 t; cvta.to.shared.u64 t, %1; cvt.u32.u64 %0, t; }" : "=r"(a) : "l"(p));
    return a;
}
#define CP_ASYNC16(s, g) asm volatile("cp.async.cg.shared.global [%0], [%1], 16;" :: "r"(s), "l"(g))
#define CP_COMMIT()      asm volatile("cp.async.commit_group;")
#define CP_WAIT1()       asm volatile("cp.async.wait_group 1;")
#define CP_WAIT0()       asm volatile("cp.async.wait_group 0;")

#define LDSM4(r0, r1, r2, r3, addr) \
    asm volatile("ldmatrix.sync.aligned.m8n8.x4.shared.b16 {%0,%1,%2,%3}, [%4];" \
        : "=r"(r0), "=r"(r1), "=r"(r2), "=r"(r3) : "r"(addr))

#define MMA16816(c, a, b0, b1) \
    asm volatile("mma.sync.aligned.m16n8k16.row.col.f32.bf16.bf16.f32 " \
        "{%0,%1,%2,%3}, {%4,%5,%6,%7}, {%8,%9}, {%0,%1,%2,%3};" \
        : "+f"((c)[0]), "+f"((c)[1]), "+f"((c)[2]), "+f"((c)[3]) \
        : "r"((a)[0]), "r"((a)[1]), "r"((a)[2]), "r"((a)[3]), "r"(b0), "r"(b1))

// ============================================================
// 1) fused prep+pack: sq, adaptive k, and x -> [hi|lo] bf16
// ============================================================
__global__ void preppack_kernel(const float* __restrict__ x,
                                const float* __restrict__ W_tau,
                                const float* __restrict__ b_tau) {
    int row = blockIdx.x;
    const float* xr = x + (size_t)row * D_X;
    __nv_bfloat16* P = g_xp + (size_t)row * KPACK;
    float s = 0.f, tt = 0.f;
    for (int i = threadIdx.x; i < D_X; i += 128) {
        float v = xr[i];
        s  = fmaf(v, v, s);
        tt = fmaf(v, W_tau[i], tt);
        __nv_bfloat16 h = __float2bfloat16(v);
        __nv_bfloat16 l = __float2bfloat16(v - __bfloat162float(h));
        P[i]       = h;
        P[D_X + i] = l;
    }
    #pragma unroll
    for (int o = 16; o > 0; o >>= 1) {
        s  += __shfl_xor_sync(~0u, s, o);
        tt += __shfl_xor_sync(~0u, tt, o);
    }
    __shared__ float sh[8];
    int w = threadIdx.x >> 5, l = threadIdx.x & 31;
    if (l == 0) { sh[w] = s; sh[4 + w] = tt; }
    __syncthreads();
    if (threadIdx.x == 0) {
        float S = sh[0] + sh[1] + sh[2] + sh[3];
        float T = sh[4] + sh[5] + sh[6] + sh[7] + b_tau[0];
        g_sq[row] = S;
        float tau = 1.f / (1.f + expf(-T));
        float kf  = rintf(16.f - 12.f * tau);
        kf = fminf(fmaxf(kf, 1.f), 16.f);
        g_k[row] = (int)kf;
    }
}

// 0b) pack W_proj^T -> [hi|lo] bf16  (W is [D_X][H_N] row-major)
__global__ void packw_kernel(const float* __restrict__ W) {
    int i = blockIdx.x * 256 + threadIdx.x;
    int k = i / H_N, n = i % H_N;
    float f = W[i];
    __nv_bfloat16 h = __float2bfloat16(f);
    __nv_bfloat16 l = __float2bfloat16(f - __bfloat162float(h));
    g_wp[(size_t)n * KPACK + k]       = h;
    g_wp[(size_t)n * KPACK + D_X + k] = l;
}

// ============================================================
// shared 128x128 GEMM mainloop: 4 warps (2x2), warp tile 64x64,
// virtual K = 1152 via 18 stages of 64 with offset maps.
// ============================================================
__device__ __forceinline__ void stage_load(uint32_t sbase,
                                           const __nv_bfloat16* gA,
                                           const __nv_bfloat16* gB, int tid) {
    #pragma unroll
    for (int it = 0; it < 8; it++) {
        int idx = tid + it * 128;
        int r = idx >> 3, c = idx & 7;
        uint32_t off = (uint32_t)(r * 128 + c * 16);
        off ^= (off >> 3) & 0x70;
        CP_ASYNC16(sbase + off,         (const char*)(gA + (size_t)r * KPACK) + c * 16);
        CP_ASYNC16(sbase + 16384 + off, (const char*)(gB + (size_t)r * KPACK) + c * 16);
    }
}

__device__ __forceinline__ void gemm_tile(uint32_t stage_base,
    const __nv_bfloat16* gA0, const __nv_bfloat16* gB0, int tid,
    const uint32_t arow_off[4], const uint32_t arow_x[4],
    const uint32_t brow_off[4], const uint32_t brow_x[4],
    uint32_t a_hi, uint32_t b_hi, float acc[4][8][4]) {

    #pragma unroll
    for (int i = 0; i < 4; i++)
        #pragma unroll
        for (int j = 0; j < 8; j++)
            #pragma unroll
            for (int q = 0; q < 4; q++) acc[i][j][q] = 0.f;

    stage_load(stage_base,           gA0 + aOffE(0), gB0 + bOffE(0), tid); CP_COMMIT();
    stage_load(stage_base + STAGE_B, gA0 + aOffE(1), gB0 + bOffE(1), tid); CP_COMMIT();

    for (int s = 0; s < NKSTAGE; s++) {
        if (s + 2 < NKSTAGE) { CP_WAIT1(); } else { CP_WAIT0(); }
        __syncthreads();
        if (s + 2 < NKSTAGE) {
            stage_load(stage_base + ((s + 2) % 3) * STAGE_B,
                       gA0 + aOffE(s + 2), gB0 + bOffE(s + 2), tid);
            CP_COMMIT();
        }
        uint32_t stA = stage_base + (s % 3) * STAGE_B;
        uint32_t stB = stA + 16384;
        #pragma unroll
        for (int kk = 0; kk < 4; kk++) {
            uint32_t a[4][4], b[4][4];
            #pragma unroll
            for (int i = 0; i < 4; i++) {
                uint32_t ck = (uint32_t)(2 * kk) + a_hi;
                uint32_t ad = stA + arow_off[i] + ((ck ^ arow_x[i]) << 4);
                LDSM4(a[i][0], a[i][1], a[i][2], a[i][3], ad);
            }
            #pragma unroll
            for (int p = 0; p < 4; p++) {
                uint32_t ck = (uint32_t)(2 * kk) + b_hi;
                uint32_t ad = stB + brow_off[p] + ((ck ^ brow_x[p]) << 4);
                LDSM4(b[p][0], b[p][1], b[p][2], b[p][3], ad);
            }
            #pragma unroll
            for (int i = 0; i < 4; i++)
                #pragma unroll
                for (int j = 0; j < 8; j++)
                    MMA16816(acc[i][j], a[i], b[j >> 1][(j & 1) * 2], b[j >> 1][(j & 1) * 2 + 1]);
        }
    }
}

// ============================================================
// 3) knn: grid (64, 32) -> 2048 CTAs (6.92 waves at 2 CTA/SM),
//    128 rows x 256 cols per CTA; running u64 top-16 per row
// ============================================================
__global__ __launch_bounds__(128, 2) void knn_kernel() {
    extern __shared__ char smem[];
    uint32_t smem_base = smem_u32(smem);
    float* sqj = (float*)smem;
    int tid = threadIdx.x, lane = tid & 31, warp = tid >> 5;
    int wm = warp >> 1, wn = warp & 1;

    int rowBase  = blockIdx.x * MTILE;
    int colStart = blockIdx.y * JCHUNK;

    uint32_t a_hi = (uint32_t)((lane >> 4) & 1);
    uint32_t b_hi = (uint32_t)((lane >> 3) & 1);
    int aRow = wm * 64 + (lane & 15);
    int bRow = wn * 64 + (lane & 7) + (((lane >> 4) & 1) << 3);
    uint32_t arow_off[4], arow_x[4], brow_off[4], brow_x[4];
    #pragma unroll
    for (int i = 0; i < 4; i++) { int r = aRow + i * 16; arow_off[i] = r * 128; arow_x[i] = r & 7; }
    #pragma unroll
    for (int p = 0; p < 4; p++) { int r = bRow + p * 16; brow_off[p] = r * 128; brow_x[p] = r & 7; }

    u64 key[16];
    #pragma unroll
    for (int p = 0; p < 16; p++) key[p] = ~0ull;

    const __nv_bfloat16* gA0 = g_xp + (size_t)rowBase * KPACK;

    for (int t = 0; t < NT_PER; t++) {
        int colBase = colStart + t * NTILE;
        __syncthreads();                     // protect prev sD/sqj reads
        sqj[tid] = g_sq[colBase + tid];
        const __nv_bfloat16* gB0 = g_xp + (size_t)colBase * KPACK;

        float acc[4][8][4];
        gemm_tile(smem_base + 1024, gA0, gB0, tid,
                  arow_off, arow_x, brow_off, brow_x, a_hi, b_hi, acc);

        // ---- epilogue: acc -> smem d-tile -> owner top-16 scan ----
        __syncthreads();                     // all warps done reading stage bufs
        float* sD = (float*)(smem + 1024);
        int r0l = wm * 64 + (lane >> 2);
        int c0l = wn * 64 + (lane & 3) * 2;
        #pragma unroll
        for (int i = 0; i < 4; i++) {
            int r = r0l + i * 16;
            #pragma unroll
            for (int j = 0; j < 8; j++) {
                int c = c0l + j * 8;
                sD[r * 129 + c]           = acc[i][j][0];
                sD[r * 129 + c + 1]       = acc[i][j][1];
                sD[(r + 8) * 129 + c]     = acc[i][j][2];
                sD[(r + 8) * 129 + c + 1] = acc[i][j][3];
            }
        }
        __syncthreads();
        #pragma unroll 4
        for (int c = 0; c < 128; c++) {
            float d = fmaf(-2.f, sD[tid * 129 + c], sqj[c]);
            u64 kk64 = pack_key(d, colBase + c);
            if (kk64 < key[15]) {
                u64 v = kk64;
                #pragma unroll
                for (int p = 0; p < 16; p++) {
                    if (v < key[p]) { u64 tmp = key[p]; key[p] = v; v = tmp; }
                }
            }
        }
    }

    size_t base = ((size_t)blockIdx.y * B_N + rowBase + tid) * KMAX;
    #pragma unroll
    for (int p = 0; p < 16; p++) g_pk[base + p] = key[p];
}

// ============================================================
// 2) proj via mma: h = relu(x @ W_proj + b_proj)
// ============================================================
__global__ __launch_bounds__(128, 2) void projmma_kernel(const float* __restrict__ b_proj) {
    extern __shared__ char smem[];
    uint32_t smem_base = smem_u32(smem);
    int tid = threadIdx.x, lane = tid & 31, warp = tid >> 5;
    int wm = warp >> 1, wn = warp & 1;

    int rowBase = blockIdx.x * MTILE;
    int colTile = blockIdx.y * NTILE;

    uint32_t a_hi = (uint32_t)((lane >> 4) & 1);
    uint32_t b_hi = (uint32_t)((lane >> 3) & 1);
    int aRow = wm * 64 + (lane & 15);
    int bRow = wn * 64 + (lane & 7) + (((lane >> 4) & 1) << 3);
    uint32_t arow_off[4], arow_x[4], brow_off[4], brow_x[4];
    #pragma unroll
    for (int i = 0; i < 4; i++) { int r = aRow + i * 16; arow_off[i] = r * 128; arow_x[i] = r & 7; }
    #pragma unroll
    for (int p = 0; p < 4; p++) { int r = bRow + p * 16; brow_off[p] = r * 128; brow_x[p] = r & 7; }

    float acc[4][8][4];
    gemm_tile(smem_base + 1024,
              g_xp + (size_t)rowBase * KPACK,
              g_wp + (size_t)colTile * KPACK, tid,
              arow_off, arow_x, brow_off, brow_x, a_hi, b_hi, acc);

    int r0l = rowBase + wm * 64 + (lane >> 2);
    int c0l = colTile + wn * 64 + (lane & 3) * 2;
    #pragma unroll
    for (int j = 0; j < 8; j++) {
        int c = c0l + j * 8;
        float bp0 = b_proj[c], bp1 = b_proj[c + 1];
        #pragma unroll
        for (int i = 0; i < 4; i++) {
            int r = r0l + i * 16;
            g_h[(size_t)r * H_N + c]           = fmaxf(acc[i][j][0] + bp0, 0.f);
            g_h[(size_t)r * H_N + c + 1]       = fmaxf(acc[i][j][1] + bp1, 0.f);
            g_h[(size_t)(r + 8) * H_N + c]     = fmaxf(acc[i][j][2] + bp0, 0.f);
            g_h[(size_t)(r + 8) * H_N + c + 1] = fmaxf(acc[i][j][3] + bp1, 0.f);
        }
    }
}

// ============================================================
// 4) single-pass merge of 32 sorted packed lists per row
//    (whole 128-B lines via 8 x ulonglong2, early-break in regs)
// ============================================================
__global__ void merge_kernel() {
    int row = blockIdx.x * 128 + threadIdx.x;
    u64 key[16];
    #pragma unroll
    for (int p = 0; p < 16; p++) key[p] = ~0ull;
    for (int s = 0; s < JSPLIT; s++) {
        const u64* L = g_pk + ((size_t)s * B_N + row) * KMAX;
        ulonglong2 v[8];
        #pragma unroll
        for (int q = 0; q < 8; q++) v[q] = *(const ulonglong2*)(L + q * 2);
        #pragma unroll
        for (int q = 0; q < 8; q++) {
            u64 a = v[q].x;
            if (a >= key[15]) break;
            #pragma unroll
            for (int p = 0; p < 16; p++)
                if (a < key[p]) { u64 tmp = key[p]; key[p] = a; a = tmp; }
            u64 b = v[q].y;
            if (b >= key[15]) break;
            #pragma unroll
            for (int p = 0; p < 16; p++)
                if (b < key[p]) { u64 tmp = key[p]; key[p] = b; b = tmp; }
        }
    }
    #pragma unroll
    for (int p = 0; p < 16; p++) g_idx[(size_t)row * KMAX + p] = (int)(key[p] & 0xFFFFFFFFull);
}

// ============================================================
// 5) fused: agg gather + residual + LayerNorm + fc
// ============================================================
__global__ __launch_bounds__(256) void resln_kernel(const float* __restrict__ W_res,
                                                    const float* __restrict__ b_res,
                                                    const float* __restrict__ ln_g,
                                                    const float* __restrict__ ln_b,
                                                    const float* __restrict__ W_fc,
                                                    const float* __restrict__ b_fc,
                                                    float* __restrict__ out) {
    __shared__ float sAgg[16][256];
    __shared__ float sZ[16][256];
    __shared__ float sG[256], sBn[256], sWfc[256 * 6], sbfc[6];
    __shared__ int sidx[16][16];
    __shared__ int sK[16];
    __shared__ float sKi[16];
    int j = threadIdx.x;
    int r0 = blockIdx.x * 16;

    { int rr = j >> 4, q = j & 15; sidx[rr][q] = g_idx[(size_t)(r0 + rr) * KMAX + q]; }
    if (j < 16) { int k = g_k[r0 + j]; sK[j] = k; sKi[j] = 1.f / (float)k; }
    sG[j] = ln_g[j]; sBn[j] = ln_b[j];
    for (int l = j; l < 256 * 6; l += 256) sWfc[l] = W_fc[l];
    if (j < 6) sbfc[j] = b_fc[j];
    float br = b_res[j];
    __syncthreads();

    for (int r = 0; r < 16; r++) {
        int k = sK[r];
        float s = 0.f;
        for (int t = 0; t < k; t++) s += g_h[(size_t)sidx[r][t] * H_N + j];
        sAgg[r][j] = s * sKi[r];
    }
    __syncthreads();

    float acc[16];
    #pragma unroll
    for (int r = 0; r < 16; r++) acc[r] = 0.f;
    for (int t = 0; t < 256; t++) {
        float w = W_res[(size_t)t * H_N + j];
        #pragma unroll
        for (int r = 0; r < 16; r++) acc[r] = fmaf(sAgg[r][t], w, acc[r]);
    }
    #pragma unroll
    for (int r = 0; r < 16; r++) {
        float rv = fmaxf(acc[r] + br, 0.f);
        sZ[r][j] = g_h[(size_t)(r0 + r) * H_N + j] + rv;
    }
    __syncthreads();

    int wid = j >> 5, lane = j & 31;
    for (int rr = 0; rr < 2; rr++) {
        int lr = wid * 2 + rr;
        int row = r0 + lr;
        float zv[8]; float s = 0.f, s2 = 0.f;
        #pragma unroll
        for (int q = 0; q < 8; q++) {
            zv[q] = sZ[lr][lane + q * 32];
            s += zv[q]; s2 = fmaf(zv[q], zv[q], s2);
        }
        #pragma unroll
        for (int o = 16; o > 0; o >>= 1) {
            s  += __shfl_xor_sync(~0u, s,  o);
            s2 += __shfl_xor_sync(~0u, s2, o);
        }
        float mu   = s * (1.f / 256.f);
        float var  = s2 * (1.f / 256.f) - mu * mu;
        float rstd = 1.0f / sqrtf(var + 1e-5f);
        float po[6] = {0, 0, 0, 0, 0, 0};
        #pragma unroll
        for (int q = 0; q < 8; q++) {
            int tcol = lane + q * 32;
            float a = (zv[q] - mu) * rstd * sG[tcol] + sBn[tcol];
            #pragma unroll
            for (int c = 0; c < 6; c++) po[c] = fmaf(a, sWfc[tcol * 6 + c], po[c]);
        }
        #pragma unroll
        for (int c = 0; c < 6; c++) {
            #pragma unroll
            for (int o = 16; o > 0; o >>= 1) po[c] += __shfl_xor_sync(~0u, po[c], o);
        }
        if (lane == 0) {
            #pragma unroll
            for (int c = 0; c < 6; c++) out[(size_t)row * C_N + c] = po[c] + sbfc[c];
        }
    }
}

// ============================================================
extern "C" void kernel_launch(void* const* d_in, const int* in_sizes, int n_in,
                              void* d_out, int out_size) {
    const float* x      = (const float*)d_in[0];
    const float* W_proj = (const float*)d_in[1];
    const float* b_proj = (const float*)d_in[2];
    const float* W_tau  = (const float*)d_in[3];
    const float* b_tau  = (const float*)d_in[4];
    const float* W_res  = (const float*)d_in[5];
    const float* b_res  = (const float*)d_in[6];
    const float* ln_g   = (const float*)d_in[7];
    const float* ln_b   = (const float*)d_in[8];
    const float* W_fc   = (const float*)d_in[9];
    const float* b_fc   = (const float*)d_in[10];
    float* out = (float*)d_out;

    cudaFuncSetAttribute(knn_kernel,     cudaFuncAttributeMaxDynamicSharedMemorySize, KNN_SMEM);
    cudaFuncSetAttribute(projmma_kernel, cudaFuncAttributeMaxDynamicSharedMemorySize, KNN_SMEM);

    preppack_kernel<<<B_N, 128>>>(x, W_tau, b_tau);
    packw_kernel<<<(D_X * H_N) / 256, 256>>>(W_proj);
    projmma_kernel<<<dim3(B_N / MTILE, H_N / NTILE), 128, KNN_SMEM>>>(b_proj);
    knn_kernel<<<dim3(B_N / MTILE, JSPLIT), 128, KNN_SMEM>>>();
    merge_kernel<<<B_N / 128, 128>>>();
    resln_kernel<<<B_N / 16, 256>>>(W_res, b_res, ln_g, ln_b, W_fc, b_fc, out);
}

// round 11
// speedup vs baseline: 1.5538x; 1.0415x over previous
#include <cuda_runtime.h>
#include <cuda_bf16.h>
#include <math_constants.h>
#include <math.h>
#include <stdint.h>

#define B_N   8192
#define D_X   384
#define H_N   256
#define C_N   6
#define KMAX  16
#define JSPLIT 32
#define JCHUNK (B_N / JSPLIT)      // 256
#define MTILE 128
#define NTILE 128
#define NT_PER (JCHUNK / NTILE)    // 2
#define KPACK (2 * D_X)            // 768 stored ([hi|lo])
#define KSTEP 64
#define NKSTAGE 18                 // 3-term virtual K = 1152
#define STAGE_B 32768
#define KNN_SMEM (1024 + 3 * STAGE_B)  // 99328

// -------- device scratch --------
__device__ float g_sq[B_N];
__device__ int   g_k[B_N];
__device__ __align__(16) __nv_bfloat16 g_xp[(size_t)B_N * KPACK];
__device__ __align__(16) __nv_bfloat16 g_wp[(size_t)H_N * KPACK];
__device__ float g_h[(size_t)B_N * H_N];
__device__ __align__(128) unsigned long long g_pk[(size_t)JSPLIT * B_N * KMAX];  // 33.5 MB
__device__ int   g_idx[(size_t)B_N * KMAX];

typedef unsigned long long u64;

__device__ __forceinline__ u64 pack_key(float d, int j) {
    uint32_t k = __float_as_uint(d);
    k ^= (uint32_t)(((int)k >> 31)) | 0x80000000u;   // total-order map
    return ((u64)k << 32) | (uint32_t)j;
}

// virtual-K stage -> element offset in packed array
__device__ __forceinline__ int aOffE(int s) { return (s < 6 ? s : s - 6) * KSTEP; }   // [hi|hi|lo]
__device__ __forceinline__ int bOffE(int s) { return (s < 12 ? s : s - 12) * KSTEP; } // [hi|lo|hi]

// ================= PTX helpers =================
__device__ __forceinline__ uint32_t smem_u32(const void* p) {
    uint32_t a;
    asm("{ .reg .u64 t; cvta.to.shared.u64 t, %1; cvt.u32.u64 %0, t; }" : "=r"(a) : "l"(p));
    return a;
}
#define CP_ASYNC16(s, g) asm volatile("cp.async.cg.shared.global [%0], [%1], 16;" :: "r"(s), "l"(g))
#define CP_COMMIT()      asm volatile("cp.async.commit_group;")
#define CP_WAIT1()       asm volatile("cp.async.wait_group 1;")
#define CP_WAIT0()       asm volatile("cp.async.wait_group 0;")

#define LDSM4(r0, r1, r2, r3, addr) \
    asm volatile("ldmatrix.sync.aligned.m8n8.x4.shared.b16 {%0,%1,%2,%3}, [%4];" \
        : "=r"(r0), "=r"(r1), "=r"(r2), "=r"(r3) : "r"(addr))

#define MMA16816(c, a, b0, b1) \
    asm volatile("mma.sync.aligned.m16n8k16.row.col.f32.bf16.bf16.f32 " \
        "{%0,%1,%2,%3}, {%4,%5,%6,%7}, {%8,%9}, {%0,%1,%2,%3};" \
        : "+f"((c)[0]), "+f"((c)[1]), "+f"((c)[2]), "+f"((c)[3]) \
        : "r"((a)[0]), "r"((a)[1]), "r"((a)[2]), "r"((a)[3]), "r"(b0), "r"(b1))

// ============================================================
// 1) fused prep+pack: sq, adaptive k, and x -> [hi|lo] bf16
// ============================================================
__global__ void preppack_kernel(const float* __restrict__ x,
                                const float* __restrict__ W_tau,
                                const float* __restrict__ b_tau) {
    int row = blockIdx.x;
    const float* xr = x + (size_t)row * D_X;
    __nv_bfloat16* P = g_xp + (size_t)row * KPACK;
    float s = 0.f, tt = 0.f;
    for (int i = threadIdx.x; i < D_X; i += 128) {
        float v = xr[i];
        s  = fmaf(v, v, s);
        tt = fmaf(v, W_tau[i], tt);
        __nv_bfloat16 h = __float2bfloat16(v);
        __nv_bfloat16 l = __float2bfloat16(v - __bfloat162float(h));
        P[i]       = h;
        P[D_X + i] = l;
    }
    #pragma unroll
    for (int o = 16; o > 0; o >>= 1) {
        s  += __shfl_xor_sync(~0u, s, o);
        tt += __shfl_xor_sync(~0u, tt, o);
    }
    __shared__ float sh[8];
    int w = threadIdx.x >> 5, l = threadIdx.x & 31;
    if (l == 0) { sh[w] = s; sh[4 + w] = tt; }
    __syncthreads();
    if (threadIdx.x == 0) {
        float S = sh[0] + sh[1] + sh[2] + sh[3];
        float T = sh[4] + sh[5] + sh[6] + sh[7] + b_tau[0];
        g_sq[row] = S;
        float tau = 1.f / (1.f + expf(-T));
        float kf  = rintf(16.f - 12.f * tau);
        kf = fminf(fmaxf(kf, 1.f), 16.f);
        g_k[row] = (int)kf;
    }
}

// 0b) pack W_proj^T -> [hi|lo] bf16  (W is [D_X][H_N] row-major)
__global__ void packw_kernel(const float* __restrict__ W) {
    int i = blockIdx.x * 256 + threadIdx.x;
    int k = i / H_N, n = i % H_N;
    float f = W[i];
    __nv_bfloat16 h = __float2bfloat16(f);
    __nv_bfloat16 l = __float2bfloat16(f - __bfloat162float(h));
    g_wp[(size_t)n * KPACK + k]       = h;
    g_wp[(size_t)n * KPACK + D_X + k] = l;
}

// ============================================================
// shared 128x128 GEMM mainloop: 4 warps (2x2), warp tile 64x64,
// virtual K = 1152 via 18 stages of 64 with offset maps.
// ============================================================
__device__ __forceinline__ void stage_load(uint32_t sbase,
                                           const __nv_bfloat16* gA,
                                           const __nv_bfloat16* gB, int tid) {
    #pragma unroll
    for (int it = 0; it < 8; it++) {
        int idx = tid + it * 128;
        int r = idx >> 3, c = idx & 7;
        uint32_t off = (uint32_t)(r * 128 + c * 16);
        off ^= (off >> 3) & 0x70;
        CP_ASYNC16(sbase + off,         (const char*)(gA + (size_t)r * KPACK) + c * 16);
        CP_ASYNC16(sbase + 16384 + off, (const char*)(gB + (size_t)r * KPACK) + c * 16);
    }
}

__device__ __forceinline__ void gemm_tile(uint32_t stage_base,
    const __nv_bfloat16* gA0, const __nv_bfloat16* gB0, int tid,
    const uint32_t arow_off[4], const uint32_t arow_x[4],
    const uint32_t brow_off[4], const uint32_t brow_x[4],
    uint32_t a_hi, uint32_t b_hi, float acc[4][8][4]) {

    #pragma unroll
    for (int i = 0; i < 4; i++)
        #pragma unroll
        for (int j = 0; j < 8; j++)
            #pragma unroll
            for (int q = 0; q < 4; q++) acc[i][j][q] = 0.f;

    stage_load(stage_base,           gA0 + aOffE(0), gB0 + bOffE(0), tid); CP_COMMIT();
    stage_load(stage_base + STAGE_B, gA0 + aOffE(1), gB0 + bOffE(1), tid); CP_COMMIT();

    for (int s = 0; s < NKSTAGE; s++) {
        if (s + 2 < NKSTAGE) { CP_WAIT1(); } else { CP_WAIT0(); }
        __syncthreads();
        if (s + 2 < NKSTAGE) {
            stage_load(stage_base + ((s + 2) % 3) * STAGE_B,
                       gA0 + aOffE(s + 2), gB0 + bOffE(s + 2), tid);
            CP_COMMIT();
        }
        uint32_t stA = stage_base + (s % 3) * STAGE_B;
        uint32_t stB = stA + 16384;
        #pragma unroll
        for (int kk = 0; kk < 4; kk++) {
            uint32_t a[4][4], b[4][4];
            #pragma unroll
            for (int i = 0; i < 4; i++) {
                uint32_t ck = (uint32_t)(2 * kk) + a_hi;
                uint32_t ad = stA + arow_off[i] + ((ck ^ arow_x[i]) << 4);
                LDSM4(a[i][0], a[i][1], a[i][2], a[i][3], ad);
            }
            #pragma unroll
            for (int p = 0; p < 4; p++) {
                uint32_t ck = (uint32_t)(2 * kk) + b_hi;
                uint32_t ad = stB + brow_off[p] + ((ck ^ brow_x[p]) << 4);
                LDSM4(b[p][0], b[p][1], b[p][2], b[p][3], ad);
            }
            #pragma unroll
            for (int i = 0; i < 4; i++)
                #pragma unroll
                for (int j = 0; j < 8; j++)
                    MMA16816(acc[i][j], a[i], b[j >> 1][(j & 1) * 2], b[j >> 1][(j & 1) * 2 + 1]);
        }
    }
}

// ============================================================
// 3) knn: grid (64, 32); float-compare epilogue (ALU-light),
//    pack to u64 keys only at the final write.
// ============================================================
__global__ __launch_bounds__(128, 2) void knn_kernel() {
    extern __shared__ char smem[];
    uint32_t smem_base = smem_u32(smem);
    float* sqj = (float*)smem;
    int tid = threadIdx.x, lane = tid & 31, warp = tid >> 5;
    int wm = warp >> 1, wn = warp & 1;

    int rowBase  = blockIdx.x * MTILE;
    int colStart = blockIdx.y * JCHUNK;

    uint32_t a_hi = (uint32_t)((lane >> 4) & 1);
    uint32_t b_hi = (uint32_t)((lane >> 3) & 1);
    int aRow = wm * 64 + (lane & 15);
    int bRow = wn * 64 + (lane & 7) + (((lane >> 4) & 1) << 3);
    uint32_t arow_off[4], arow_x[4], brow_off[4], brow_x[4];
    #pragma unroll
    for (int i = 0; i < 4; i++) { int r = aRow + i * 16; arow_off[i] = r * 128; arow_x[i] = r & 7; }
    #pragma unroll
    for (int p = 0; p < 4; p++) { int r = bRow + p * 16; brow_off[p] = r * 128; brow_x[p] = r & 7; }

    float dist[16]; int idxr[16];
    #pragma unroll
    for (int p = 0; p < 16; p++) { dist[p] = CUDART_INF_F; idxr[p] = 0x7fffffff; }

    const __nv_bfloat16* gA0 = g_xp + (size_t)rowBase * KPACK;

    for (int t = 0; t < NT_PER; t++) {
        int colBase = colStart + t * NTILE;
        __syncthreads();                     // protect prev sD/sqj reads
        sqj[tid] = g_sq[colBase + tid];
        const __nv_bfloat16* gB0 = g_xp + (size_t)colBase * KPACK;

        float acc[4][8][4];
        gemm_tile(smem_base + 1024, gA0, gB0, tid,
                  arow_off, arow_x, brow_off, brow_x, a_hi, b_hi, acc);

        // ---- epilogue: acc -> smem d-tile -> owner top-16 scan ----
        __syncthreads();                     // all warps done reading stage bufs
        float* sD = (float*)(smem + 1024);
        int r0l = wm * 64 + (lane >> 2);
        int c0l = wn * 64 + (lane & 3) * 2;
        #pragma unroll
        for (int i = 0; i < 4; i++) {
            int r = r0l + i * 16;
            #pragma unroll
            for (int j = 0; j < 8; j++) {
                int c = c0l + j * 8;
                sD[r * 129 + c]           = acc[i][j][0];
                sD[r * 129 + c + 1]       = acc[i][j][1];
                sD[(r + 8) * 129 + c]     = acc[i][j][2];
                sD[(r + 8) * 129 + c + 1] = acc[i][j][3];
            }
        }
        __syncthreads();
        // strict < with ascending-j scan => lexicographic (dist, idx) ordering
        #pragma unroll 4
        for (int c = 0; c < 128; c++) {
            float d = fmaf(-2.f, sD[tid * 129 + c], sqj[c]);
            if (d < dist[15]) {
                float dd = d; int jj = colBase + c;
                #pragma unroll
                for (int p = 0; p < 16; p++) {
                    if (dd < dist[p]) {
                        float td = dist[p]; dist[p] = dd; dd = td;
                        int   tj = idxr[p]; idxr[p] = jj; jj = tj;
                    }
                }
            }
        }
    }

    size_t base = ((size_t)blockIdx.y * B_N + rowBase + tid) * KMAX;
    #pragma unroll
    for (int p = 0; p < 16; p++) g_pk[base + p] = pack_key(dist[p], idxr[p]);
}

// ============================================================
// 2) proj via mma: h = relu(x @ W_proj + b_proj)
// ============================================================
__global__ __launch_bounds__(128, 2) void projmma_kernel(const float* __restrict__ b_proj) {
    extern __shared__ char smem[];
    uint32_t smem_base = smem_u32(smem);
    int tid = threadIdx.x, lane = tid & 31, warp = tid >> 5;
    int wm = warp >> 1, wn = warp & 1;

    int rowBase = blockIdx.x * MTILE;
    int colTile = blockIdx.y * NTILE;

    uint32_t a_hi = (uint32_t)((lane >> 4) & 1);
    uint32_t b_hi = (uint32_t)((lane >> 3) & 1);
    int aRow = wm * 64 + (lane & 15);
    int bRow = wn * 64 + (lane & 7) + (((lane >> 4) & 1) << 3);
    uint32_t arow_off[4], arow_x[4], brow_off[4], brow_x[4];
    #pragma unroll
    for (int i = 0; i < 4; i++) { int r = aRow + i * 16; arow_off[i] = r * 128; arow_x[i] = r & 7; }
    #pragma unroll
    for (int p = 0; p < 4; p++) { int r = bRow + p * 16; brow_off[p] = r * 128; brow_x[p] = r & 7; }

    float acc[4][8][4];
    gemm_tile(smem_base + 1024,
              g_xp + (size_t)rowBase * KPACK,
              g_wp + (size_t)colTile * KPACK, tid,
              arow_off, arow_x, brow_off, brow_x, a_hi, b_hi, acc);

    int r0l = rowBase + wm * 64 + (lane >> 2);
    int c0l = colTile + wn * 64 + (lane & 3) * 2;
    #pragma unroll
    for (int j = 0; j < 8; j++) {
        int c = c0l + j * 8;
        float bp0 = b_proj[c], bp1 = b_proj[c + 1];
        #pragma unroll
        for (int i = 0; i < 4; i++) {
            int r = r0l + i * 16;
            g_h[(size_t)r * H_N + c]           = fmaxf(acc[i][j][0] + bp0, 0.f);
            g_h[(size_t)r * H_N + c + 1]       = fmaxf(acc[i][j][1] + bp1, 0.f);
            g_h[(size_t)(r + 8) * H_N + c]     = fmaxf(acc[i][j][2] + bp0, 0.f);
            g_h[(size_t)(r + 8) * H_N + c + 1] = fmaxf(acc[i][j][3] + bp1, 0.f);
        }
    }
}

// ============================================================
// 4) single-pass merge of 32 sorted packed lists per row
//    (whole 128-B lines via 8 x ulonglong2, early-break in regs)
// ============================================================
__global__ void merge_kernel() {
    int row = blockIdx.x * 128 + threadIdx.x;
    u64 key[16];
    #pragma unroll
    for (int p = 0; p < 16; p++) key[p] = ~0ull;
    for (int s = 0; s < JSPLIT; s++) {
        const u64* L = g_pk + ((size_t)s * B_N + row) * KMAX;
        ulonglong2 v[8];
        #pragma unroll
        for (int q = 0; q < 8; q++) v[q] = *(const ulonglong2*)(L + q * 2);
        #pragma unroll
        for (int q = 0; q < 8; q++) {
            u64 a = v[q].x;
            if (a >= key[15]) break;
            #pragma unroll
            for (int p = 0; p < 16; p++)
                if (a < key[p]) { u64 tmp = key[p]; key[p] = a; a = tmp; }
            u64 b = v[q].y;
            if (b >= key[15]) break;
            #pragma unroll
            for (int p = 0; p < 16; p++)
                if (b < key[p]) { u64 tmp = key[p]; key[p] = b; b = tmp; }
        }
    }
    #pragma unroll
    for (int p = 0; p < 16; p++) g_idx[(size_t)row * KMAX + p] = (int)(key[p] & 0xFFFFFFFFull);
}

// ============================================================
// 5) fused: agg gather + residual + LayerNorm + fc
// ============================================================
__global__ __launch_bounds__(256) void resln_kernel(const float* __restrict__ W_res,
                                                    const float* __restrict__ b_res,
                                                    const float* __restrict__ ln_g,
                                                    const float* __restrict__ ln_b,
                                                    const float* __restrict__ W_fc,
                                                    const float* __restrict__ b_fc,
                                                    float* __restrict__ out) {
    __shared__ float sAgg[16][256];
    __shared__ float sZ[16][256];
    __shared__ float sG[256], sBn[256], sWfc[256 * 6], sbfc[6];
    __shared__ int sidx[16][16];
    __shared__ int sK[16];
    __shared__ float sKi[16];
    int j = threadIdx.x;
    int r0 = blockIdx.x * 16;

    { int rr = j >> 4, q = j & 15; sidx[rr][q] = g_idx[(size_t)(r0 + rr) * KMAX + q]; }
    if (j < 16) { int k = g_k[r0 + j]; sK[j] = k; sKi[j] = 1.f / (float)k; }
    sG[j] = ln_g[j]; sBn[j] = ln_b[j];
    for (int l = j; l < 256 * 6; l += 256) sWfc[l] = W_fc[l];
    if (j < 6) sbfc[j] = b_fc[j];
    float br = b_res[j];
    __syncthreads();

    for (int r = 0; r < 16; r++) {
        int k = sK[r];
        float s = 0.f;
        for (int t = 0; t < k; t++) s += g_h[(size_t)sidx[r][t] * H_N + j];
        sAgg[r][j] = s * sKi[r];
    }
    __syncthreads();

    float acc[16];
    #pragma unroll
    for (int r = 0; r < 16; r++) acc[r] = 0.f;
    for (int t = 0; t < 256; t++) {
        float w = W_res[(size_t)t * H_N + j];
        #pragma unroll
        for (int r = 0; r < 16; r++) acc[r] = fmaf(sAgg[r][t], w, acc[r]);
    }
    #pragma unroll
    for (int r = 0; r < 16; r++) {
        float rv = fmaxf(acc[r] + br, 0.f);
        sZ[r][j] = g_h[(size_t)(r0 + r) * H_N + j] + rv;
    }
    __syncthreads();

    int wid = j >> 5, lane = j & 31;
    for (int rr = 0; rr < 2; rr++) {
        int lr = wid * 2 + rr;
        int row = r0 + lr;
        float zv[8]; float s = 0.f, s2 = 0.f;
        #pragma unroll
        for (int q = 0; q < 8; q++) {
            zv[q] = sZ[lr][lane + q * 32];
            s += zv[q]; s2 = fmaf(zv[q], zv[q], s2);
        }
        #pragma unroll
        for (int o = 16; o > 0; o >>= 1) {
            s  += __shfl_xor_sync(~0u, s,  o);
            s2 += __shfl_xor_sync(~0u, s2, o);
        }
        float mu   = s * (1.f / 256.f);
        float var  = s2 * (1.f / 256.f) - mu * mu;
        float rstd = 1.0f / sqrtf(var + 1e-5f);
        float po[6] = {0, 0, 0, 0, 0, 0};
        #pragma unroll
        for (int q = 0; q < 8; q++) {
            int tcol = lane + q * 32;
            float a = (zv[q] - mu) * rstd * sG[tcol] + sBn[tcol];
            #pragma unroll
            for (int c = 0; c < 6; c++) po[c] = fmaf(a, sWfc[tcol * 6 + c], po[c]);
        }
        #pragma unroll
        for (int c = 0; c < 6; c++) {
            #pragma unroll
            for (int o = 16; o > 0; o >>= 1) po[c] += __shfl_xor_sync(~0u, po[c], o);
        }
        if (lane == 0) {
            #pragma unroll
            for (int c = 0; c < 6; c++) out[(size_t)row * C_N + c] = po[c] + sbfc[c];
        }
    }
}

// ============================================================
extern "C" void kernel_launch(void* const* d_in, const int* in_sizes, int n_in,
                              void* d_out, int out_size) {
    const float* x      = (const float*)d_in[0];
    const float* W_proj = (const float*)d_in[1];
    const float* b_proj = (const float*)d_in[2];
    const float* W_tau  = (const float*)d_in[3];
    const float* b_tau  = (const float*)d_in[4];
    const float* W_res  = (const float*)d_in[5];
    const float* b_res  = (const float*)d_in[6];
    const float* ln_g   = (const float*)d_in[7];
    const float* ln_b   = (const float*)d_in[8];
    const float* W_fc   = (const float*)d_in[9];
    const float* b_fc   = (const float*)d_in[10];
    float* out = (float*)d_out;

    cudaFuncSetAttribute(knn_kernel,     cudaFuncAttributeMaxDynamicSharedMemorySize, KNN_SMEM);
    cudaFuncSetAttribute(projmma_kernel, cudaFuncAttributeMaxDynamicSharedMemorySize, KNN_SMEM);

    preppack_kernel<<<B_N, 128>>>(x, W_tau, b_tau);
    packw_kernel<<<(D_X * H_N) / 256, 256>>>(W_proj);
    projmma_kernel<<<dim3(B_N / MTILE, H_N / NTILE), 128, KNN_SMEM>>>(b_proj);
    knn_kernel<<<dim3(B_N / MTILE, JSPLIT), 128, KNN_SMEM>>>();
    merge_kernel<<<B_N / 128, 128>>>();
    resln_kernel<<<B_N / 16, 256>>>(W_res, b_res, ln_g, ln_b, W_fc, b_fc, out);
}

// round 13
// speedup vs baseline: 1.5812x; 1.0176x over previous
#include <cuda_runtime.h>
#include <cuda_bf16.h>
#include <math_constants.h>
#include <math.h>
#include <stdint.h>

#define B_N   8192
#define D_X   384
#define H_N   256
#define C_N   6
#define KMAX  16
#define JSPLIT 32
#define JCHUNK (B_N / JSPLIT)      // 256
#define MTILE 128
#define NTILE 128
#define NT_PER (JCHUNK / NTILE)    // 2
#define KPACK (2 * D_X)            // 768 stored ([hi|lo])
#define KSTEP 64
#define NKSTAGE 18                 // 3-term virtual K = 1152
#define STAGE_B 32768
#define KNN_SMEM (1024 + 3 * STAGE_B)  // 99328

// -------- device scratch --------
__device__ float g_sq[B_N];
__device__ int   g_k[B_N];
__device__ __align__(16) __nv_bfloat16 g_xp[(size_t)B_N * KPACK];
__device__ __align__(16) __nv_bfloat16 g_wp[(size_t)H_N * KPACK];
__device__ float g_h[(size_t)B_N * H_N];
__device__ __align__(128) unsigned long long g_pk[(size_t)JSPLIT * B_N * KMAX];  // 33.5 MB

typedef unsigned long long u64;

__device__ __forceinline__ u64 pack_key(float d, int j) {
    uint32_t k = __float_as_uint(d);
    k ^= (uint32_t)(((int)k >> 31)) | 0x80000000u;   // total-order map
    return ((u64)k << 32) | (uint32_t)j;
}

// virtual-K stage -> element offset in packed array
__device__ __forceinline__ int aOffE(int s) { return (s < 6 ? s : s - 6) * KSTEP; }   // [hi|hi|lo]
__device__ __forceinline__ int bOffE(int s) { return (s < 12 ? s : s - 12) * KSTEP; } // [hi|lo|hi]

// ================= PTX helpers =================
__device__ __forceinline__ uint32_t smem_u32(const void* p) {
    uint32_t a;
    asm("{ .reg .u64 t; cvta.to.shared.u64 t, %1; cvt.u32.u64 %0, t; }" : "=r"(a) : "l"(p));
    return a;
}
#define CP_ASYNC16(s, g) asm volatile("cp.async.cg.shared.global [%0], [%1], 16;" :: "r"(s), "l"(g))
#define CP_COMMIT()      asm volatile("cp.async.commit_group;")
#define CP_WAIT1()       asm volatile("cp.async.wait_group 1;")
#define CP_WAIT0()       asm volatile("cp.async.wait_group 0;")

#define LDSM4(r0, r1, r2, r3, addr) \
    asm volatile("ldmatrix.sync.aligned.m8n8.x4.shared.b16 {%0,%1,%2,%3}, [%4];" \
        : "=r"(r0), "=r"(r1), "=r"(r2), "=r"(r3) : "r"(addr))

#define MMA16816(c, a, b0, b1) \
    asm volatile("mma.sync.aligned.m16n8k16.row.col.f32.bf16.bf16.f32 " \
        "{%0,%1,%2,%3}, {%4,%5,%6,%7}, {%8,%9}, {%0,%1,%2,%3};" \
        : "+f"((c)[0]), "+f"((c)[1]), "+f"((c)[2]), "+f"((c)[3]) \
        : "r"((a)[0]), "r"((a)[1]), "r"((a)[2]), "r"((a)[3]), "r"(b0), "r"(b1))

// ============================================================
// 1) fused prep+pack (+ packw in tail blocks)
// ============================================================
__global__ void preppack_kernel(const float* __restrict__ x,
                                const float* __restrict__ W_tau,
                                const float* __restrict__ b_tau,
                                const float* __restrict__ W_proj) {
    if (blockIdx.x >= B_N) {
        // packw: W_proj^T -> [hi|lo] bf16  (W is [D_X][H_N] row-major)
        int i = (blockIdx.x - B_N) * 128 + threadIdx.x;   // 0..98303
        int k = i / H_N, n = i % H_N;
        float f = W_proj[i];
        __nv_bfloat16 h = __float2bfloat16(f);
        __nv_bfloat16 l = __float2bfloat16(f - __bfloat162float(h));
        g_wp[(size_t)n * KPACK + k]       = h;
        g_wp[(size_t)n * KPACK + D_X + k] = l;
        return;
    }
    int row = blockIdx.x;
    const float* xr = x + (size_t)row * D_X;
    __nv_bfloat16* P = g_xp + (size_t)row * KPACK;
    float s = 0.f, tt = 0.f;
    for (int i = threadIdx.x; i < D_X; i += 128) {
        float v = xr[i];
        s  = fmaf(v, v, s);
        tt = fmaf(v, W_tau[i], tt);
        __nv_bfloat16 h = __float2bfloat16(v);
        __nv_bfloat16 l = __float2bfloat16(v - __bfloat162float(h));
        P[i]       = h;
        P[D_X + i] = l;
    }
    #pragma unroll
    for (int o = 16; o > 0; o >>= 1) {
        s  += __shfl_xor_sync(~0u, s, o);
        tt += __shfl_xor_sync(~0u, tt, o);
    }
    __shared__ float sh[8];
    int w = threadIdx.x >> 5, l = threadIdx.x & 31;
    if (l == 0) { sh[w] = s; sh[4 + w] = tt; }
    __syncthreads();
    if (threadIdx.x == 0) {
        float S = sh[0] + sh[1] + sh[2] + sh[3];
        float T = sh[4] + sh[5] + sh[6] + sh[7] + b_tau[0];
        g_sq[row] = S;
        float tau = 1.f / (1.f + expf(-T));
        float kf  = rintf(16.f - 12.f * tau);
        kf = fminf(fmaxf(kf, 1.f), 16.f);
        g_k[row] = (int)kf;
    }
}

// ============================================================
// shared 128x128 GEMM mainloop: 4 warps (2x2), warp tile 64x64,
// virtual K = 1152 via 18 stages of 64 with offset maps.
// ============================================================
__device__ __forceinline__ void stage_load(uint32_t sbase,
                                           const __nv_bfloat16* gA,
                                           const __nv_bfloat16* gB, int tid) {
    #pragma unroll
    for (int it = 0; it < 8; it++) {
        int idx = tid + it * 128;
        int r = idx >> 3, c = idx & 7;
        uint32_t off = (uint32_t)(r * 128 + c * 16);
        off ^= (off >> 3) & 0x70;
        CP_ASYNC16(sbase + off,         (const char*)(gA + (size_t)r * KPACK) + c * 16);
        CP_ASYNC16(sbase + 16384 + off, (const char*)(gB + (size_t)r * KPACK) + c * 16);
    }
}

__device__ __forceinline__ void gemm_tile(uint32_t stage_base,
    const __nv_bfloat16* gA0, const __nv_bfloat16* gB0, int tid,
    const uint32_t arow_off[4], const uint32_t arow_x[4],
    const uint32_t brow_off[4], const uint32_t brow_x[4],
    uint32_t a_hi, uint32_t b_hi, float acc[4][8][4]) {

    #pragma unroll
    for (int i = 0; i < 4; i++)
        #pragma unroll
        for (int j = 0; j < 8; j++)
            #pragma unroll
            for (int q = 0; q < 4; q++) acc[i][j][q] = 0.f;

    stage_load(stage_base,           gA0 + aOffE(0), gB0 + bOffE(0), tid); CP_COMMIT();
    stage_load(stage_base + STAGE_B, gA0 + aOffE(1), gB0 + bOffE(1), tid); CP_COMMIT();

    for (int s = 0; s < NKSTAGE; s++) {
        if (s + 2 < NKSTAGE) { CP_WAIT1(); } else { CP_WAIT0(); }
        __syncthreads();
        if (s + 2 < NKSTAGE) {
            stage_load(stage_base + ((s + 2) % 3) * STAGE_B,
                       gA0 + aOffE(s + 2), gB0 + bOffE(s + 2), tid);
            CP_COMMIT();
        }
        uint32_t stA = stage_base + (s % 3) * STAGE_B;
        uint32_t stB = stA + 16384;
        #pragma unroll
        for (int kk = 0; kk < 4; kk++) {
            uint32_t a[4][4], b[4][4];
            #pragma unroll
            for (int i = 0; i < 4; i++) {
                uint32_t ck = (uint32_t)(2 * kk) + a_hi;
                uint32_t ad = stA + arow_off[i] + ((ck ^ arow_x[i]) << 4);
                LDSM4(a[i][0], a[i][1], a[i][2], a[i][3], ad);
            }
            #pragma unroll
            for (int p = 0; p < 4; p++) {
                uint32_t ck = (uint32_t)(2 * kk) + b_hi;
                uint32_t ad = stB + brow_off[p] + ((ck ^ brow_x[p]) << 4);
                LDSM4(b[p][0], b[p][1], b[p][2], b[p][3], ad);
            }
            #pragma unroll
            for (int i = 0; i < 4; i++)
                #pragma unroll
                for (int j = 0; j < 8; j++)
                    MMA16816(acc[i][j], a[i], b[j >> 1][(j & 1) * 2], b[j >> 1][(j & 1) * 2 + 1]);
        }
    }
}

// ============================================================
// 2+3) unified GEMM kernel: grid (64, JSPLIT+2)
//   y <  JSPLIT : knn tile (float-compare epilogue, packed-key write)
//   y >= JSPLIT : proj tile -> g_h
// ============================================================
__global__ __launch_bounds__(128, 2) void gemm_kernel(const float* __restrict__ b_proj) {
    extern __shared__ char smem[];
    uint32_t smem_base = smem_u32(smem);
    int tid = threadIdx.x, lane = tid & 31, warp = tid >> 5;
    int wm = warp >> 1, wn = warp & 1;
    int rowBase = blockIdx.x * MTILE;

    uint32_t a_hi = (uint32_t)((lane >> 4) & 1);
    uint32_t b_hi = (uint32_t)((lane >> 3) & 1);
    int aRow = wm * 64 + (lane & 15);
    int bRow = wn * 64 + (lane & 7) + (((lane >> 4) & 1) << 3);
    uint32_t arow_off[4], arow_x[4], brow_off[4], brow_x[4];
    #pragma unroll
    for (int i = 0; i < 4; i++) { int r = aRow + i * 16; arow_off[i] = r * 128; arow_x[i] = r & 7; }
    #pragma unroll
    for (int p = 0; p < 4; p++) { int r = bRow + p * 16; brow_off[p] = r * 128; brow_x[p] = r & 7; }

    if (blockIdx.y >= JSPLIT) {
        // ---------- proj tile ----------
        int colTile = (blockIdx.y - JSPLIT) * NTILE;
        float acc[4][8][4];
        gemm_tile(smem_base + 1024,
                  g_xp + (size_t)rowBase * KPACK,
                  g_wp + (size_t)colTile * KPACK, tid,
                  arow_off, arow_x, brow_off, brow_x, a_hi, b_hi, acc);

        int r0l = rowBase + wm * 64 + (lane >> 2);
        int c0l = colTile + wn * 64 + (lane & 3) * 2;
        #pragma unroll
        for (int j = 0; j < 8; j++) {
            int c = c0l + j * 8;
            float bp0 = b_proj[c], bp1 = b_proj[c + 1];
            #pragma unroll
            for (int i = 0; i < 4; i++) {
                int r = r0l + i * 16;
                g_h[(size_t)r * H_N + c]           = fmaxf(acc[i][j][0] + bp0, 0.f);
                g_h[(size_t)r * H_N + c + 1]       = fmaxf(acc[i][j][1] + bp1, 0.f);
                g_h[(size_t)(r + 8) * H_N + c]     = fmaxf(acc[i][j][2] + bp0, 0.f);
                g_h[(size_t)(r + 8) * H_N + c + 1] = fmaxf(acc[i][j][3] + bp1, 0.f);
            }
        }
        return;
    }

    // ---------- knn tiles ----------
    float* sqj = (float*)smem;
    int colStart = blockIdx.y * JCHUNK;

    float dist[16]; int idxr[16];
    #pragma unroll
    for (int p = 0; p < 16; p++) { dist[p] = CUDART_INF_F; idxr[p] = 0x7fffffff; }

    const __nv_bfloat16* gA0 = g_xp + (size_t)rowBase * KPACK;

    for (int t = 0; t < NT_PER; t++) {
        int colBase = colStart + t * NTILE;
        __syncthreads();                     // protect prev sD/sqj reads
        sqj[tid] = g_sq[colBase + tid];
        const __nv_bfloat16* gB0 = g_xp + (size_t)colBase * KPACK;

        float acc[4][8][4];
        gemm_tile(smem_base + 1024, gA0, gB0, tid,
                  arow_off, arow_x, brow_off, brow_x, a_hi, b_hi, acc);

        // ---- epilogue: acc -> smem d-tile -> owner top-16 scan ----
        __syncthreads();                     // all warps done reading stage bufs
        float* sD = (float*)(smem + 1024);
        int r0l = wm * 64 + (lane >> 2);
        int c0l = wn * 64 + (lane & 3) * 2;
        #pragma unroll
        for (int i = 0; i < 4; i++) {
            int r = r0l + i * 16;
            #pragma unroll
            for (int j = 0; j < 8; j++) {
                int c = c0l + j * 8;
                sD[r * 129 + c]           = acc[i][j][0];
                sD[r * 129 + c + 1]       = acc[i][j][1];
                sD[(r + 8) * 129 + c]     = acc[i][j][2];
                sD[(r + 8) * 129 + c + 1] = acc[i][j][3];
            }
        }
        __syncthreads();
        // strict < with ascending-j scan => lexicographic (dist, idx) ordering
        #pragma unroll 4
        for (int c = 0; c < 128; c++) {
            float d = fmaf(-2.f, sD[tid * 129 + c], sqj[c]);
            if (d < dist[15]) {
                float dd = d; int jj = colBase + c;
                #pragma unroll
                for (int p = 0; p < 16; p++) {
                    if (dd < dist[p]) {
                        float td = dist[p]; dist[p] = dd; dd = td;
                        int   tj = idxr[p]; idxr[p] = jj; jj = tj;
                    }
                }
            }
        }
    }

    size_t base = ((size_t)blockIdx.y * B_N + rowBase + tid) * KMAX;
    #pragma unroll
    for (int p = 0; p < 16; p++) g_pk[base + p] = pack_key(dist[p], idxr[p]);
}

// ============================================================
// 4) fused: merge(32 lists) + agg gather + residual + LN + fc
// ============================================================
__global__ __launch_bounds__(256) void resln_kernel(const float* __restrict__ W_res,
                                                    const float* __restrict__ b_res,
                                                    const float* __restrict__ ln_g,
                                                    const float* __restrict__ ln_b,
                                                    const float* __restrict__ W_fc,
                                                    const float* __restrict__ b_fc,
                                                    float* __restrict__ out) {
    __shared__ float sAgg[16][256];
    __shared__ float sZ[16][256];
    __shared__ float sG[256], sBn[256], sWfc[256 * 6], sbfc[6];
    __shared__ int sidx[16][16];
    __shared__ int sK[16];
    __shared__ float sKi[16];
    int j = threadIdx.x;
    int r0 = blockIdx.x * 16;

    // merge 32 sorted packed lists for this block's 16 rows (thread j<16 owns row j)
    if (j < 16) {
        int row = r0 + j;
        u64 key[16];
        #pragma unroll
        for (int p = 0; p < 16; p++) key[p] = ~0ull;
        for (int s = 0; s < JSPLIT; s++) {
            const u64* L = g_pk + ((size_t)s * B_N + row) * KMAX;
            ulonglong2 v[8];
            #pragma unroll
            for (int q = 0; q < 8; q++) v[q] = *(const ulonglong2*)(L + q * 2);
            #pragma unroll
            for (int q = 0; q < 8; q++) {
                u64 a = v[q].x;
                if (a >= key[15]) break;
                #pragma unroll
                for (int p = 0; p < 16; p++)
                    if (a < key[p]) { u64 tmp = key[p]; key[p] = a; a = tmp; }
                u64 b = v[q].y;
                if (b >= key[15]) break;
                #pragma unroll
                for (int p = 0; p < 16; p++)
                    if (b < key[p]) { u64 tmp = key[p]; key[p] = b; b = tmp; }
            }
        }
        #pragma unroll
        for (int p = 0; p < 16; p++) sidx[j][p] = (int)(key[p] & 0xFFFFFFFFull);
        int k = g_k[row]; sK[j] = k; sKi[j] = 1.f / (float)k;
    }
    sG[j] = ln_g[j]; sBn[j] = ln_b[j];
    for (int l = j; l < 256 * 6; l += 256) sWfc[l] = W_fc[l];
    if (j < 6) sbfc[j] = b_fc[j];
    float br = b_res[j];
    __syncthreads();

    for (int r = 0; r < 16; r++) {
        int k = sK[r];
        float s = 0.f;
        for (int t = 0; t < k; t++) s += g_h[(size_t)sidx[r][t] * H_N + j];
        sAgg[r][j] = s * sKi[r];
    }
    __syncthreads();

    float acc[16];
    #pragma unroll
    for (int r = 0; r < 16; r++) acc[r] = 0.f;
    for (int t = 0; t < 256; t++) {
        float w = W_res[(size_t)t * H_N + j];
        #pragma unroll
        for (int r = 0; r < 16; r++) acc[r] = fmaf(sAgg[r][t], w, acc[r]);
    }
    #pragma unroll
    for (int r = 0; r < 16; r++) {
        float rv = fmaxf(acc[r] + br, 0.f);
        sZ[r][j] = g_h[(size_t)(r0 + r) * H_N + j] + rv;
    }
    __syncthreads();

    int wid = j >> 5, lane = j & 31;
    for (int rr = 0; rr < 2; rr++) {
        int lr = wid * 2 + rr;
        int row = r0 + lr;
        float zv[8]; float s = 0.f, s2 = 0.f;
        #pragma unroll
        for (int q = 0; q < 8; q++) {
            zv[q] = sZ[lr][lane + q * 32];
            s += zv[q]; s2 = fmaf(zv[q], zv[q], s2);
        }
        #pragma unroll
        for (int o = 16; o > 0; o >>= 1) {
            s  += __shfl_xor_sync(~0u, s,  o);
            s2 += __shfl_xor_sync(~0u, s2, o);
        }
        float mu   = s * (1.f / 256.f);
        float var  = s2 * (1.f / 256.f) - mu * mu;
        float rstd = 1.0f / sqrtf(var + 1e-5f);
        float po[6] = {0, 0, 0, 0, 0, 0};
        #pragma unroll
        for (int q = 0; q < 8; q++) {
            int tcol = lane + q * 32;
            float a = (zv[q] - mu) * rstd * sG[tcol] + sBn[tcol];
            #pragma unroll
            for (int c = 0; c < 6; c++) po[c] = fmaf(a, sWfc[tcol * 6 + c], po[c]);
        }
        #pragma unroll
        for (int c = 0; c < 6; c++) {
            #pragma unroll
            for (int o = 16; o > 0; o >>= 1) po[c] += __shfl_xor_sync(~0u, po[c], o);
        }
        if (lane == 0) {
            #pragma unroll
            for (int c = 0; c < 6; c++) out[(size_t)row * C_N + c] = po[c] + sbfc[c];
        }
    }
}

// ============================================================
extern "C" void kernel_launch(void* const* d_in, const int* in_sizes, int n_in,
                              void* d_out, int out_size) {
    const float* x      = (const float*)d_in[0];
    const float* W_proj = (const float*)d_in[1];
    const float* b_proj = (const float*)d_in[2];
    const float* W_tau  = (const float*)d_in[3];
    const float* b_tau  = (const float*)d_in[4];
    const float* W_res  = (const float*)d_in[5];
    const float* b_res  = (const float*)d_in[6];
    const float* ln_g   = (const float*)d_in[7];
    const float* ln_b   = (const float*)d_in[8];
    const float* W_fc   = (const float*)d_in[9];
    const float* b_fc   = (const float*)d_in[10];
    float* out = (float*)d_out;

    cudaFuncSetAttribute(gemm_kernel, cudaFuncAttributeMaxDynamicSharedMemorySize, KNN_SMEM);

    preppack_kernel<<<B_N + (D_X * H_N) / 128, 128>>>(x, W_tau, b_tau, W_proj);
    gemm_kernel<<<dim3(B_N / MTILE, JSPLIT + H_N / NTILE), 128, KNN_SMEM>>>(b_proj);
    resln_kernel<<<B_N / 16, 256>>>(W_res, b_res, ln_g, ln_b, W_fc, b_fc, out);
}

// round 15
// speedup vs baseline: 1.6414x; 1.0381x over previous
#include <cuda_runtime.h>
#include <cuda_bf16.h>
#include <math_constants.h>
#include <math.h>
#include <stdint.h>

#define B_N   8192
#define D_X   384
#define H_N   256
#define C_N   6
#define KMAX  16
#define NBLK  64
#define NPAIR (NBLK * (NBLK + 1) / 2)   // 2080
#define NPROJ (NBLK * 2)                // wait: 64 rowblocks x 2 coltiles = 128
#define MTILE 128
#define NTILE 128
#define KPACK (2 * D_X)            // 768 stored ([hi|lo])
#define KSTEP 64
#define NKSTAGE 18                 // 3-term virtual K = 1152
#define STAGE_B 32768
#define KNN_SMEM (1024 + 3 * STAGE_B)  // 99328

// -------- device scratch --------
__device__ float g_sq[B_N];
__device__ int   g_k[B_N];
__device__ __align__(16) __nv_bfloat16 g_xp[(size_t)B_N * KPACK];
__device__ __align__(16) __nv_bfloat16 g_wp[(size_t)H_N * KPACK];
__device__ float g_h[(size_t)B_N * H_N];
__device__ __align__(128) unsigned long long g_pk[(size_t)NBLK * B_N * KMAX];  // 67 MB
__device__ int   g_k_unused;

typedef unsigned long long u64;

__device__ __forceinline__ u64 pack_key(float d, int j) {
    uint32_t k = __float_as_uint(d);
    k ^= (uint32_t)(((int)k >> 31)) | 0x80000000u;   // total-order map
    return ((u64)k << 32) | (uint32_t)j;
}

// virtual-K stage -> element offset (3-term: hi.hi, hi.lo, lo.hi)
__device__ __forceinline__ int aOffE(int s) { return (s < 6 ? s : s - 6) * KSTEP; }   // [hi|hi|lo]
__device__ __forceinline__ int bOffE(int s) { return (s < 12 ? s : s - 12) * KSTEP; } // [hi|lo|hi]

// ================= PTX helpers =================
__device__ __forceinline__ uint32_t smem_u32(const void* p) {
    uint32_t a;
    asm("{ .reg .u64 t; cvta.to.shared.u64 t, %1; cvt.u32.u64 %0, t; }" : "=r"(a) : "l"(p));
    return a;
}
#define CP_ASYNC16(s, g) asm volatile("cp.async.cg.shared.global [%0], [%1], 16;" :: "r"(s), "l"(g))
#define CP_COMMIT()      asm volatile("cp.async.commit_group;")
#define CP_WAIT1()       asm volatile("cp.async.wait_group 1;")
#define CP_WAIT0()       asm volatile("cp.async.wait_group 0;")

#define LDSM4(r0, r1, r2, r3, addr) \
    asm volatile("ldmatrix.sync.aligned.m8n8.x4.shared.b16 {%0,%1,%2,%3}, [%4];" \
        : "=r"(r0), "=r"(r1), "=r"(r2), "=r"(r3) : "r"(addr))

#define MMA16816(c, a, b0, b1) \
    asm volatile("mma.sync.aligned.m16n8k16.row.col.f32.bf16.bf16.f32 " \
        "{%0,%1,%2,%3}, {%4,%5,%6,%7}, {%8,%9}, {%0,%1,%2,%3};" \
        : "+f"((c)[0]), "+f"((c)[1]), "+f"((c)[2]), "+f"((c)[3]) \
        : "r"((a)[0]), "r"((a)[1]), "r"((a)[2]), "r"((a)[3]), "r"(b0), "r"(b1))

// ============================================================
// 1) fused prep+pack (+ packw in tail blocks)
// ============================================================
__global__ void preppack_kernel(const float* __restrict__ x,
                                const float* __restrict__ W_tau,
                                const float* __restrict__ b_tau,
                                const float* __restrict__ W_proj) {
    if (blockIdx.x >= B_N) {
        int i = (blockIdx.x - B_N) * 128 + threadIdx.x;   // 0..98303
        int k = i / H_N, n = i % H_N;
        float f = W_proj[i];
        __nv_bfloat16 h = __float2bfloat16(f);
        __nv_bfloat16 l = __float2bfloat16(f - __bfloat162float(h));
        g_wp[(size_t)n * KPACK + k]       = h;
        g_wp[(size_t)n * KPACK + D_X + k] = l;
        return;
    }
    int row = blockIdx.x;
    const float* xr = x + (size_t)row * D_X;
    __nv_bfloat16* P = g_xp + (size_t)row * KPACK;
    float s = 0.f, tt = 0.f;
    for (int i = threadIdx.x; i < D_X; i += 128) {
        float v = xr[i];
        s  = fmaf(v, v, s);
        tt = fmaf(v, W_tau[i], tt);
        __nv_bfloat16 h = __float2bfloat16(v);
        __nv_bfloat16 l = __float2bfloat16(v - __bfloat162float(h));
        P[i]       = h;
        P[D_X + i] = l;
    }
    #pragma unroll
    for (int o = 16; o > 0; o >>= 1) {
        s  += __shfl_xor_sync(~0u, s, o);
        tt += __shfl_xor_sync(~0u, tt, o);
    }
    __shared__ float sh[8];
    int w = threadIdx.x >> 5, l = threadIdx.x & 31;
    if (l == 0) { sh[w] = s; sh[4 + w] = tt; }
    __syncthreads();
    if (threadIdx.x == 0) {
        float S = sh[0] + sh[1] + sh[2] + sh[3];
        float T = sh[4] + sh[5] + sh[6] + sh[7] + b_tau[0];
        g_sq[row] = S;
        float tau = 1.f / (1.f + expf(-T));
        float kf  = rintf(16.f - 12.f * tau);
        kf = fminf(fmaxf(kf, 1.f), 16.f);
        g_k[row] = (int)kf;
    }
}

// ============================================================
// shared 128x128 GEMM mainloop: 4 warps (2x2), warp tile 64x64
// ============================================================
__device__ __forceinline__ void stage_load(uint32_t sbase,
                                           const __nv_bfloat16* gA,
                                           const __nv_bfloat16* gB, int tid) {
    #pragma unroll
    for (int it = 0; it < 8; it++) {
        int idx = tid + it * 128;
        int r = idx >> 3, c = idx & 7;
        uint32_t off = (uint32_t)(r * 128 + c * 16);
        off ^= (off >> 3) & 0x70;
        CP_ASYNC16(sbase + off,         (const char*)(gA + (size_t)r * KPACK) + c * 16);
        CP_ASYNC16(sbase + 16384 + off, (const char*)(gB + (size_t)r * KPACK) + c * 16);
    }
}

__device__ __forceinline__ void gemm_tile(uint32_t stage_base,
    const __nv_bfloat16* gA0, const __nv_bfloat16* gB0, int tid,
    const uint32_t arow_off[4], const uint32_t arow_x[4],
    const uint32_t brow_off[4], const uint32_t brow_x[4],
    uint32_t a_hi, uint32_t b_hi, float acc[4][8][4]) {

    #pragma unroll
    for (int i = 0; i < 4; i++)
        #pragma unroll
        for (int j = 0; j < 8; j++)
            #pragma unroll
            for (int q = 0; q < 4; q++) acc[i][j][q] = 0.f;

    stage_load(stage_base,           gA0 + aOffE(0), gB0 + bOffE(0), tid); CP_COMMIT();
    stage_load(stage_base + STAGE_B, gA0 + aOffE(1), gB0 + bOffE(1), tid); CP_COMMIT();

    for (int s = 0; s < NKSTAGE; s++) {
        if (s + 2 < NKSTAGE) { CP_WAIT1(); } else { CP_WAIT0(); }
        __syncthreads();
        if (s + 2 < NKSTAGE) {
            stage_load(stage_base + ((s + 2) % 3) * STAGE_B,
                       gA0 + aOffE(s + 2), gB0 + bOffE(s + 2), tid);
            CP_COMMIT();
        }
        uint32_t stA = stage_base + (s % 3) * STAGE_B;
        uint32_t stB = stA + 16384;
        #pragma unroll
        for (int kk = 0; kk < 4; kk++) {
            uint32_t a[4][4], b[4][4];
            #pragma unroll
            for (int i = 0; i < 4; i++) {
                uint32_t ck = (uint32_t)(2 * kk) + a_hi;
                uint32_t ad = stA + arow_off[i] + ((ck ^ arow_x[i]) << 4);
                LDSM4(a[i][0], a[i][1], a[i][2], a[i][3], ad);
            }
            #pragma unroll
            for (int p = 0; p < 4; p++) {
                uint32_t ck = (uint32_t)(2 * kk) + b_hi;
                uint32_t ad = stB + brow_off[p] + ((ck ^ brow_x[p]) << 4);
                LDSM4(b[p][0], b[p][1], b[p][2], b[p][3], ad);
            }
            #pragma unroll
            for (int i = 0; i < 4; i++)
                #pragma unroll
                for (int j = 0; j < 8; j++)
                    MMA16816(acc[i][j], a[i], b[j >> 1][(j & 1) * 2], b[j >> 1][(j & 1) * 2 + 1]);
        }
    }
}

// ============================================================
// 2+3) unified GEMM kernel, 1D grid NPAIR + 128:
//   x <  NPAIR : symmetric knn pair tile (dual-view top-16)
//   x >= NPAIR : proj tile -> g_h
// ============================================================
__global__ __launch_bounds__(128, 2) void gemm_kernel(const float* __restrict__ b_proj) {
    extern __shared__ char smem[];
    uint32_t smem_base = smem_u32(smem);
    int tid = threadIdx.x, lane = tid & 31, warp = tid >> 5;
    int wm = warp >> 1, wn = warp & 1;

    uint32_t a_hi = (uint32_t)((lane >> 4) & 1);
    uint32_t b_hi = (uint32_t)((lane >> 3) & 1);
    int aRow = wm * 64 + (lane & 15);
    int bRow = wn * 64 + (lane & 7) + (((lane >> 4) & 1) << 3);
    uint32_t arow_off[4], arow_x[4], brow_off[4], brow_x[4];
    #pragma unroll
    for (int i = 0; i < 4; i++) { int r = aRow + i * 16; arow_off[i] = r * 128; arow_x[i] = r & 7; }
    #pragma unroll
    for (int p = 0; p < 4; p++) { int r = bRow + p * 16; brow_off[p] = r * 128; brow_x[p] = r & 7; }

    if (blockIdx.x >= NPAIR) {
        // ---------- proj tile ----------
        int pr = blockIdx.x - NPAIR;          // 0..127
        int rowBase = (pr & 63) * MTILE;
        int colTile = (pr >> 6) * NTILE;
        float acc[4][8][4];
        gemm_tile(smem_base + 1024,
                  g_xp + (size_t)rowBase * KPACK,
                  g_wp + (size_t)colTile * KPACK, tid,
                  arow_off, arow_x, brow_off, brow_x, a_hi, b_hi, acc);

        int r0l = rowBase + wm * 64 + (lane >> 2);
        int c0l = colTile + wn * 64 + (lane & 3) * 2;
        #pragma unroll
        for (int j = 0; j < 8; j++) {
            int c = c0l + j * 8;
            float bp0 = b_proj[c], bp1 = b_proj[c + 1];
            #pragma unroll
            for (int i = 0; i < 4; i++) {
                int r = r0l + i * 16;
                g_h[(size_t)r * H_N + c]           = fmaxf(acc[i][j][0] + bp0, 0.f);
                g_h[(size_t)r * H_N + c + 1]       = fmaxf(acc[i][j][1] + bp1, 0.f);
                g_h[(size_t)(r + 8) * H_N + c]     = fmaxf(acc[i][j][2] + bp0, 0.f);
                g_h[(size_t)(r + 8) * H_N + c + 1] = fmaxf(acc[i][j][3] + bp1, 0.f);
            }
        }
        return;
    }

    // ---------- symmetric knn pair (bi <= bj) ----------
    int t = blockIdx.x;
    int bi = (int)((129.0f - sqrtf(16641.0f - 8.0f * (float)t)) * 0.5f);
    if (bi > NBLK - 1) bi = NBLK - 1;
    while (bi > 0 && t < bi * NBLK - bi * (bi - 1) / 2) bi--;
    while (t >= (bi + 1) * NBLK - (bi + 1) * bi / 2) bi++;
    int bj = bi + (t - (bi * NBLK - bi * (bi - 1) / 2));

    int rowBase = bi * MTILE;
    int colBase = bj * MTILE;

    float* sqi = (float*)smem;
    float* sqj = (float*)(smem + 512);
    sqi[tid] = g_sq[rowBase + tid];
    sqj[tid] = g_sq[colBase + tid];

    float acc[4][8][4];
    gemm_tile(smem_base + 1024,
              g_xp + (size_t)rowBase * KPACK,
              g_xp + (size_t)colBase * KPACK, tid,
              arow_off, arow_x, brow_off, brow_x, a_hi, b_hi, acc);

    __syncthreads();
    float* sD = (float*)(smem + 1024);
    int r0l = wm * 64 + (lane >> 2);
    int c0l = wn * 64 + (lane & 3) * 2;
    #pragma unroll
    for (int i = 0; i < 4; i++) {
        int r = r0l + i * 16;
        #pragma unroll
        for (int j = 0; j < 8; j++) {
            int c = c0l + j * 8;
            sD[r * 129 + c]           = acc[i][j][0];
            sD[r * 129 + c + 1]       = acc[i][j][1];
            sD[(r + 8) * 129 + c]     = acc[i][j][2];
            sD[(r + 8) * 129 + c + 1] = acc[i][j][3];
        }
    }
    __syncthreads();

    float dist[16]; int idxr[16];

    // row-side view: owner = rowBase+tid, candidates = colBase + c, drop sq_owner
    #pragma unroll
    for (int p = 0; p < 16; p++) { dist[p] = CUDART_INF_F; idxr[p] = 0x7fffffff; }
    #pragma unroll 4
    for (int c = 0; c < 128; c++) {
        float d = fmaf(-2.f, sD[tid * 129 + c], sqj[c]);
        if (d < dist[15]) {
            float dd = d; int jj = colBase + c;
            #pragma unroll
            for (int p = 0; p < 16; p++) {
                if (dd < dist[p]) {
                    float td = dist[p]; dist[p] = dd; dd = td;
                    int   tj = idxr[p]; idxr[p] = jj; jj = tj;
                }
            }
        }
    }
    {
        size_t base = ((size_t)bj * B_N + rowBase + tid) * KMAX;
        #pragma unroll
        for (int p = 0; p < 16; p++) g_pk[base + p] = pack_key(dist[p], idxr[p]);
    }

    // col-side view (off-diagonal only): owner = colBase+tid, candidates = rowBase + r
    if (bi != bj) {
        #pragma unroll
        for (int p = 0; p < 16; p++) { dist[p] = CUDART_INF_F; idxr[p] = 0x7fffffff; }
        #pragma unroll 4
        for (int r = 0; r < 128; r++) {
            float d = fmaf(-2.f, sD[r * 129 + tid], sqi[r]);
            if (d < dist[15]) {
                float dd = d; int jj = rowBase + r;
                #pragma unroll
                for (int p = 0; p < 16; p++) {
                    if (dd < dist[p]) {
                        float td = dist[p]; dist[p] = dd; dd = td;
                        int   tj = idxr[p]; idxr[p] = jj; jj = tj;
                    }
                }
            }
        }
        size_t base = ((size_t)bi * B_N + colBase + tid) * KMAX;
        #pragma unroll
        for (int p = 0; p < 16; p++) g_pk[base + p] = pack_key(dist[p], idxr[p]);
    }
}

// ============================================================
// 4) fused: merge(64 lists) + agg gather + residual + LN + fc
// ============================================================
__global__ __launch_bounds__(256) void resln_kernel(const float* __restrict__ W_res,
                                                    const float* __restrict__ b_res,
                                                    const float* __restrict__ ln_g,
                                                    const float* __restrict__ ln_b,
                                                    const float* __restrict__ W_fc,
                                                    const float* __restrict__ b_fc,
                                                    float* __restrict__ out) {
    __shared__ float sAgg[16][256];
    __shared__ float sZ[16][256];
    __shared__ float sG[256], sBn[256], sWfc[256 * 6], sbfc[6];
    __shared__ int sidx[16][16];
    __shared__ int sK[16];
    __shared__ float sKi[16];
    int j = threadIdx.x;
    int r0 = blockIdx.x * 16;

    // merge 64 sorted packed lists for this block's 16 rows (thread j<16 owns row j)
    if (j < 16) {
        int row = r0 + j;
        u64 key[16];
        #pragma unroll
        for (int p = 0; p < 16; p++) key[p] = ~0ull;
        for (int s = 0; s < NBLK; s++) {
            const u64* L = g_pk + ((size_t)s * B_N + row) * KMAX;
            ulonglong2 v[8];
            #pragma unroll
            for (int q = 0; q < 8; q++) v[q] = *(const ulonglong2*)(L + q * 2);
            #pragma unroll
            for (int q = 0; q < 8; q++) {
                u64 a = v[q].x;
                if (a >= key[15]) break;
                #pragma unroll
                for (int p = 0; p < 16; p++)
                    if (a < key[p]) { u64 tmp = key[p]; key[p] = a; a = tmp; }
                u64 b = v[q].y;
                if (b >= key[15]) break;
                #pragma unroll
                for (int p = 0; p < 16; p++)
                    if (b < key[p]) { u64 tmp = key[p]; key[p] = b; b = tmp; }
            }
        }
        #pragma unroll
        for (int p = 0; p < 16; p++) sidx[j][p] = (int)(key[p] & 0xFFFFFFFFull);
        int k = g_k[row]; sK[j] = k; sKi[j] = 1.f / (float)k;
    }
    sG[j] = ln_g[j]; sBn[j] = ln_b[j];
    for (int l = j; l < 256 * 6; l += 256) sWfc[l] = W_fc[l];
    if (j < 6) sbfc[j] = b_fc[j];
    float br = b_res[j];
    __syncthreads();

    for (int r = 0; r < 16; r++) {
        int k = sK[r];
        float s = 0.f;
        for (int t = 0; t < k; t++) s += g_h[(size_t)sidx[r][t] * H_N + j];
        sAgg[r][j] = s * sKi[r];
    }
    __syncthreads();

    float acc[16];
    #pragma unroll
    for (int r = 0; r < 16; r++) acc[r] = 0.f;
    for (int t = 0; t < 256; t++) {
        float w = W_res[(size_t)t * H_N + j];
        #pragma unroll
        for (int r = 0; r < 16; r++) acc[r] = fmaf(sAgg[r][t], w, acc[r]);
    }
    #pragma unroll
    for (int r = 0; r < 16; r++) {
        float rv = fmaxf(acc[r] + br, 0.f);
        sZ[r][j] = g_h[(size_t)(r0 + r) * H_N + j] + rv;
    }
    __syncthreads();

    int wid = j >> 5, lane = j & 31;
    for (int rr = 0; rr < 2; rr++) {
        int lr = wid * 2 + rr;
        int row = r0 + lr;
        float zv[8]; float s = 0.f, s2 = 0.f;
        #pragma unroll
        for (int q = 0; q < 8; q++) {
            zv[q] = sZ[lr][lane + q * 32];
            s += zv[q]; s2 = fmaf(zv[q], zv[q], s2);
        }
        #pragma unroll
        for (int o = 16; o > 0; o >>= 1) {
            s  += __shfl_xor_sync(~0u, s,  o);
            s2 += __shfl_xor_sync(~0u, s2, o);
        }
        float mu   = s * (1.f / 256.f);
        float var  = s2 * (1.f / 256.f) - mu * mu;
        float rstd = 1.0f / sqrtf(var + 1e-5f);
        float po[6] = {0, 0, 0, 0, 0, 0};
        #pragma unroll
        for (int q = 0; q < 8; q++) {
            int tcol = lane + q * 32;
            float a = (zv[q] - mu) * rstd * sG[tcol] + sBn[tcol];
            #pragma unroll
            for (int c = 0; c < 6; c++) po[c] = fmaf(a, sWfc[tcol * 6 + c], po[c]);
        }
        #pragma unroll
        for (int c = 0; c < 6; c++) {
            #pragma unroll
            for (int o = 16; o > 0; o >>= 1) po[c] += __shfl_xor_sync(~0u, po[c], o);
        }
        if (lane == 0) {
            #pragma unroll
            for (int c = 0; c < 6; c++) out[(size_t)row * C_N + c] = po[c] + sbfc[c];
        }
    }
}

// ============================================================
extern "C" void kernel_launch(void* const* d_in, const int* in_sizes, int n_in,
                              void* d_out, int out_size) {
    const float* x      = (const float*)d_in[0];
    const float* W_proj = (const float*)d_in[1];
    const float* b_proj = (const float*)d_in[2];
    const float* W_tau  = (const float*)d_in[3];
    const float* b_tau  = (const float*)d_in[4];
    const float* W_res  = (const float*)d_in[5];
    const float* b_res  = (const float*)d_in[6];
    const float* ln_g   = (const float*)d_in[7];
    const float* ln_b   = (const float*)d_in[8];
    const float* W_fc   = (const float*)d_in[9];
    const float* b_fc   = (const float*)d_in[10];
    float* out = (float*)d_out;

    cudaFuncSetAttribute(gemm_kernel, cudaFuncAttributeMaxDynamicSharedMemorySize, KNN_SMEM);

    preppack_kernel<<<B_N + (D_X * H_N) / 128, 128>>>(x, W_tau, b_tau, W_proj);
    gemm_kernel<<<NPAIR + 128, 128, KNN_SMEM>>>(b_proj);
    resln_kernel<<<B_N / 16, 256>>>(W_res, b_res, ln_g, ln_b, W_fc, b_fc, out);
}

// round 16
// speedup vs baseline: 1.7093x; 1.0414x over previous
#include <cuda_runtime.h>
#include <cuda_bf16.h>
#include <math_constants.h>
#include <math.h>
#include <stdint.h>

#define B_N   8192
#define D_X   384
#define H_N   256
#define C_N   6
#define KMAX  16
#define NBLK  64
#define NPAIR (NBLK * (NBLK + 1) / 2)   // 2080
#define MTILE 128
#define NTILE 128
#define KPACK (2 * D_X)            // 768 stored ([hi|lo])
#define KSTEP 64
#define NKSTAGE 18                 // 3-term virtual K = 1152
#define STAGE_B 32768
#define KNN_SMEM (1024 + 3 * STAGE_B)  // 99328

// -------- device scratch --------
__device__ float g_sq[B_N];
__device__ int   g_k[B_N];
__device__ __align__(16) __nv_bfloat16 g_xp[(size_t)B_N * KPACK];
__device__ __align__(16) __nv_bfloat16 g_wp[(size_t)H_N * KPACK];
__device__ float g_h[(size_t)B_N * H_N];
__device__ __align__(128) unsigned long long g_pk[(size_t)NBLK * B_N * KMAX];  // 67 MB

typedef unsigned long long u64;

__device__ __forceinline__ u64 pack_key(float d, int j) {
    uint32_t k = __float_as_uint(d);
    k ^= (uint32_t)(((int)k >> 31)) | 0x80000000u;   // total-order map
    return ((u64)k << 32) | (uint32_t)j;
}

// virtual-K stage -> element offset (3-term: hi.hi, hi.lo, lo.hi)
__device__ __forceinline__ int aOffE(int s) { return (s < 6 ? s : s - 6) * KSTEP; }   // [hi|hi|lo]
__device__ __forceinline__ int bOffE(int s) { return (s < 12 ? s : s - 12) * KSTEP; } // [hi|lo|hi]

// ================= PTX helpers =================
__device__ __forceinline__ uint32_t smem_u32(const void* p) {
    uint32_t a;
    asm("{ .reg .u64 t; cvta.to.shared.u64 t, %1; cvt.u32.u64 %0, t; }" : "=r"(a) : "l"(p));
    return a;
}
#define CP_ASYNC16(s, g) asm volatile("cp.async.cg.shared.global [%0], [%1], 16;" :: "r"(s), "l"(g))
#define CP_COMMIT()      asm volatile("cp.async.commit_group;")
#define CP_WAIT1()       asm volatile("cp.async.wait_group 1;")
#define CP_WAIT0()       asm volatile("cp.async.wait_group 0;")

#define LDSM4(r0, r1, r2, r3, addr) \
    asm volatile("ldmatrix.sync.aligned.m8n8.x4.shared.b16 {%0,%1,%2,%3}, [%4];" \
        : "=r"(r0), "=r"(r1), "=r"(r2), "=r"(r3) : "r"(addr))

#define MMA16816(c, a, b0, b1) \
    asm volatile("mma.sync.aligned.m16n8k16.row.col.f32.bf16.bf16.f32 " \
        "{%0,%1,%2,%3}, {%4,%5,%6,%7}, {%8,%9}, {%0,%1,%2,%3};" \
        : "+f"((c)[0]), "+f"((c)[1]), "+f"((c)[2]), "+f"((c)[3]) \
        : "r"((a)[0]), "r"((a)[1]), "r"((a)[2]), "r"((a)[3]), "r"(b0), "r"(b1))

// ============================================================
// 1) fused prep+pack (+ packw in tail blocks)
// ============================================================
__global__ void preppack_kernel(const float* __restrict__ x,
                                const float* __restrict__ W_tau,
                                const float* __restrict__ b_tau,
                                const float* __restrict__ W_proj) {
    if (blockIdx.x >= B_N) {
        int i = (blockIdx.x - B_N) * 128 + threadIdx.x;   // 0..98303
        int k = i / H_N, n = i % H_N;
        float f = W_proj[i];
        __nv_bfloat16 h = __float2bfloat16(f);
        __nv_bfloat16 l = __float2bfloat16(f - __bfloat162float(h));
        g_wp[(size_t)n * KPACK + k]       = h;
        g_wp[(size_t)n * KPACK + D_X + k] = l;
        return;
    }
    int row = blockIdx.x;
    const float* xr = x + (size_t)row * D_X;
    __nv_bfloat16* P = g_xp + (size_t)row * KPACK;
    float s = 0.f, tt = 0.f;
    for (int i = threadIdx.x; i < D_X; i += 128) {
        float v = xr[i];
        s  = fmaf(v, v, s);
        tt = fmaf(v, W_tau[i], tt);
        __nv_bfloat16 h = __float2bfloat16(v);
        __nv_bfloat16 l = __float2bfloat16(v - __bfloat162float(h));
        P[i]       = h;
        P[D_X + i] = l;
    }
    #pragma unroll
    for (int o = 16; o > 0; o >>= 1) {
        s  += __shfl_xor_sync(~0u, s, o);
        tt += __shfl_xor_sync(~0u, tt, o);
    }
    __shared__ float sh[8];
    int w = threadIdx.x >> 5, l = threadIdx.x & 31;
    if (l == 0) { sh[w] = s; sh[4 + w] = tt; }
    __syncthreads();
    if (threadIdx.x == 0) {
        float S = sh[0] + sh[1] + sh[2] + sh[3];
        float T = sh[4] + sh[5] + sh[6] + sh[7] + b_tau[0];
        g_sq[row] = S;
        float tau = 1.f / (1.f + expf(-T));
        float kf  = rintf(16.f - 12.f * tau);
        kf = fminf(fmaxf(kf, 1.f), 16.f);
        g_k[row] = (int)kf;
    }
}

// ============================================================
// shared 128x128 GEMM mainloop: 4 warps (2x2), warp tile 64x64
// ============================================================
__device__ __forceinline__ void stage_load(uint32_t sbase,
                                           const __nv_bfloat16* gA,
                                           const __nv_bfloat16* gB, int tid) {
    #pragma unroll
    for (int it = 0; it < 8; it++) {
        int idx = tid + it * 128;
        int r = idx >> 3, c = idx & 7;
        uint32_t off = (uint32_t)(r * 128 + c * 16);
        off ^= (off >> 3) & 0x70;
        CP_ASYNC16(sbase + off,         (const char*)(gA + (size_t)r * KPACK) + c * 16);
        CP_ASYNC16(sbase + 16384 + off, (const char*)(gB + (size_t)r * KPACK) + c * 16);
    }
}

__device__ __forceinline__ void gemm_tile(uint32_t stage_base,
    const __nv_bfloat16* gA0, const __nv_bfloat16* gB0, int tid,
    const uint32_t arow_off[4], const uint32_t arow_x[4],
    const uint32_t brow_off[4], const uint32_t brow_x[4],
    uint32_t a_hi, uint32_t b_hi, float acc[4][8][4]) {

    #pragma unroll
    for (int i = 0; i < 4; i++)
        #pragma unroll
        for (int j = 0; j < 8; j++)
            #pragma unroll
            for (int q = 0; q < 4; q++) acc[i][j][q] = 0.f;

    stage_load(stage_base,           gA0 + aOffE(0), gB0 + bOffE(0), tid); CP_COMMIT();
    stage_load(stage_base + STAGE_B, gA0 + aOffE(1), gB0 + bOffE(1), tid); CP_COMMIT();

    for (int s = 0; s < NKSTAGE; s++) {
        if (s + 2 < NKSTAGE) { CP_WAIT1(); } else { CP_WAIT0(); }
        __syncthreads();
        if (s + 2 < NKSTAGE) {
            stage_load(stage_base + ((s + 2) % 3) * STAGE_B,
                       gA0 + aOffE(s + 2), gB0 + bOffE(s + 2), tid);
            CP_COMMIT();
        }
        uint32_t stA = stage_base + (s % 3) * STAGE_B;
        uint32_t stB = stA + 16384;
        #pragma unroll
        for (int kk = 0; kk < 4; kk++) {
            uint32_t a[4][4], b[4][4];
            #pragma unroll
            for (int i = 0; i < 4; i++) {
                uint32_t ck = (uint32_t)(2 * kk) + a_hi;
                uint32_t ad = stA + arow_off[i] + ((ck ^ arow_x[i]) << 4);
                LDSM4(a[i][0], a[i][1], a[i][2], a[i][3], ad);
            }
            #pragma unroll
            for (int p = 0; p < 4; p++) {
                uint32_t ck = (uint32_t)(2 * kk) + b_hi;
                uint32_t ad = stB + brow_off[p] + ((ck ^ brow_x[p]) << 4);
                LDSM4(b[p][0], b[p][1], b[p][2], b[p][3], ad);
            }
            #pragma unroll
            for (int i = 0; i < 4; i++)
                #pragma unroll
                for (int j = 0; j < 8; j++)
                    MMA16816(acc[i][j], a[i], b[j >> 1][(j & 1) * 2], b[j >> 1][(j & 1) * 2 + 1]);
        }
    }
}

// ============================================================
// 2+3) unified GEMM kernel, 1D grid NPAIR + 128:
//   x <  NPAIR : symmetric knn pair tile (dual-view top-16)
//   x >= NPAIR : proj tile -> g_h
// ============================================================
__global__ __launch_bounds__(128, 2) void gemm_kernel(const float* __restrict__ b_proj) {
    extern __shared__ char smem[];
    uint32_t smem_base = smem_u32(smem);
    int tid = threadIdx.x, lane = tid & 31, warp = tid >> 5;
    int wm = warp >> 1, wn = warp & 1;

    uint32_t a_hi = (uint32_t)((lane >> 4) & 1);
    uint32_t b_hi = (uint32_t)((lane >> 3) & 1);
    int aRow = wm * 64 + (lane & 15);
    int bRow = wn * 64 + (lane & 7) + (((lane >> 4) & 1) << 3);
    uint32_t arow_off[4], arow_x[4], brow_off[4], brow_x[4];
    #pragma unroll
    for (int i = 0; i < 4; i++) { int r = aRow + i * 16; arow_off[i] = r * 128; arow_x[i] = r & 7; }
    #pragma unroll
    for (int p = 0; p < 4; p++) { int r = bRow + p * 16; brow_off[p] = r * 128; brow_x[p] = r & 7; }

    if (blockIdx.x >= NPAIR) {
        // ---------- proj tile ----------
        int pr = blockIdx.x - NPAIR;          // 0..127
        int rowBase = (pr & 63) * MTILE;
        int colTile = (pr >> 6) * NTILE;
        float acc[4][8][4];
        gemm_tile(smem_base + 1024,
                  g_xp + (size_t)rowBase * KPACK,
                  g_wp + (size_t)colTile * KPACK, tid,
                  arow_off, arow_x, brow_off, brow_x, a_hi, b_hi, acc);

        int r0l = rowBase + wm * 64 + (lane >> 2);
        int c0l = colTile + wn * 64 + (lane & 3) * 2;
        #pragma unroll
        for (int j = 0; j < 8; j++) {
            int c = c0l + j * 8;
            float bp0 = b_proj[c], bp1 = b_proj[c + 1];
            #pragma unroll
            for (int i = 0; i < 4; i++) {
                int r = r0l + i * 16;
                g_h[(size_t)r * H_N + c]           = fmaxf(acc[i][j][0] + bp0, 0.f);
                g_h[(size_t)r * H_N + c + 1]       = fmaxf(acc[i][j][1] + bp1, 0.f);
                g_h[(size_t)(r + 8) * H_N + c]     = fmaxf(acc[i][j][2] + bp0, 0.f);
                g_h[(size_t)(r + 8) * H_N + c + 1] = fmaxf(acc[i][j][3] + bp1, 0.f);
            }
        }
        return;
    }

    // ---------- symmetric knn pair (bi <= bj) ----------
    int t = blockIdx.x;
    int bi = (int)((129.0f - sqrtf(16641.0f - 8.0f * (float)t)) * 0.5f);
    if (bi > NBLK - 1) bi = NBLK - 1;
    while (bi > 0 && t < bi * NBLK - bi * (bi - 1) / 2) bi--;
    while (t >= (bi + 1) * NBLK - (bi + 1) * bi / 2) bi++;
    int bj = bi + (t - (bi * NBLK - bi * (bi - 1) / 2));

    int rowBase = bi * MTILE;
    int colBase = bj * MTILE;

    float* sqi = (float*)smem;
    float* sqj = (float*)(smem + 512);
    sqi[tid] = g_sq[rowBase + tid];
    sqj[tid] = g_sq[colBase + tid];

    float acc[4][8][4];
    gemm_tile(smem_base + 1024,
              g_xp + (size_t)rowBase * KPACK,
              g_xp + (size_t)colBase * KPACK, tid,
              arow_off, arow_x, brow_off, brow_x, a_hi, b_hi, acc);

    __syncthreads();
    float* sD = (float*)(smem + 1024);
    int r0l = wm * 64 + (lane >> 2);
    int c0l = wn * 64 + (lane & 3) * 2;
    #pragma unroll
    for (int i = 0; i < 4; i++) {
        int r = r0l + i * 16;
        #pragma unroll
        for (int j = 0; j < 8; j++) {
            int c = c0l + j * 8;
            sD[r * 129 + c]           = acc[i][j][0];
            sD[r * 129 + c + 1]       = acc[i][j][1];
            sD[(r + 8) * 129 + c]     = acc[i][j][2];
            sD[(r + 8) * 129 + c + 1] = acc[i][j][3];
        }
    }
    __syncthreads();

    float dist[16]; int idxr[16];

    // row-side view: owner = rowBase+tid, candidates = colBase + c, drop sq_owner
    #pragma unroll
    for (int p = 0; p < 16; p++) { dist[p] = CUDART_INF_F; idxr[p] = 0x7fffffff; }
    #pragma unroll 4
    for (int c = 0; c < 128; c++) {
        float d = fmaf(-2.f, sD[tid * 129 + c], sqj[c]);
        if (d < dist[15]) {
            float dd = d; int jj = colBase + c;
            #pragma unroll
            for (int p = 0; p < 16; p++) {
                if (dd < dist[p]) {
                    float td = dist[p]; dist[p] = dd; dd = td;
                    int   tj = idxr[p]; idxr[p] = jj; jj = tj;
                }
            }
        }
    }
    {
        size_t base = ((size_t)bj * B_N + rowBase + tid) * KMAX;
        #pragma unroll
        for (int p = 0; p < 16; p++) g_pk[base + p] = pack_key(dist[p], idxr[p]);
    }

    // col-side view (off-diagonal only): owner = colBase+tid, candidates = rowBase + r
    if (bi != bj) {
        #pragma unroll
        for (int p = 0; p < 16; p++) { dist[p] = CUDART_INF_F; idxr[p] = 0x7fffffff; }
        #pragma unroll 4
        for (int r = 0; r < 128; r++) {
            float d = fmaf(-2.f, sD[r * 129 + tid], sqi[r]);
            if (d < dist[15]) {
                float dd = d; int jj = rowBase + r;
                #pragma unroll
                for (int p = 0; p < 16; p++) {
                    if (dd < dist[p]) {
                        float td = dist[p]; dist[p] = dd; dd = td;
                        int   tj = idxr[p]; idxr[p] = jj; jj = tj;
                    }
                }
            }
        }
        size_t base = ((size_t)bi * B_N + colBase + tid) * KMAX;
        #pragma unroll
        for (int p = 0; p < 16; p++) g_pk[base + p] = pack_key(dist[p], idxr[p]);
    }
}

// ============================================================
// 4) fused: two-phase parallel merge(64 lists) + agg + res + LN + fc
// ============================================================
__global__ __launch_bounds__(256) void resln_kernel(const float* __restrict__ W_res,
                                                    const float* __restrict__ b_res,
                                                    const float* __restrict__ ln_g,
                                                    const float* __restrict__ ln_b,
                                                    const float* __restrict__ W_fc,
                                                    const float* __restrict__ b_fc,
                                                    float* __restrict__ out) {
    __shared__ float sAgg[16][256];
    __shared__ float sZ[16][256];          // phase A staging aliases this (16 KB)
    __shared__ float sG[256], sBn[256], sWfc[256 * 6], sbfc[6];
    __shared__ int sidx[16][16];
    __shared__ int sK[16];
    __shared__ float sKi[16];
    int j = threadIdx.x;
    int r0 = blockIdx.x * 16;
    u64* sPart = (u64*)sZ;                 // [16 rows][8 segs][16 keys] = 16 KB

    // ---- phase A: 128 threads, each merges 8 of the 64 lists for its row ----
    if (j < 128) {
        int r = j >> 3, seg = j & 7;
        int row = r0 + r;
        u64 key[16];
        #pragma unroll
        for (int p = 0; p < 16; p++) key[p] = ~0ull;
        for (int s2 = 0; s2 < 8; s2++) {
            const u64* L = g_pk + ((size_t)(seg * 8 + s2) * B_N + row) * KMAX;
            ulonglong2 v[8];
            #pragma unroll
            for (int q = 0; q < 8; q++) v[q] = *(const ulonglong2*)(L + q * 2);
            #pragma unroll
            for (int q = 0; q < 8; q++) {
                u64 a = v[q].x;
                if (a >= key[15]) break;
                #pragma unroll
                for (int p = 0; p < 16; p++)
                    if (a < key[p]) { u64 tmp = key[p]; key[p] = a; a = tmp; }
                u64 b = v[q].y;
                if (b >= key[15]) break;
                #pragma unroll
                for (int p = 0; p < 16; p++)
                    if (b < key[p]) { u64 tmp = key[p]; key[p] = b; b = tmp; }
            }
        }
        #pragma unroll
        for (int p = 0; p < 16; p++) sPart[(size_t)(r * 8 + seg) * 16 + p] = key[p];
    }
    sG[j] = ln_g[j]; sBn[j] = ln_b[j];
    for (int l = j; l < 256 * 6; l += 256) sWfc[l] = W_fc[l];
    if (j < 6) sbfc[j] = b_fc[j];
    float br = b_res[j];
    __syncthreads();

    // ---- phase B: 16 threads merge the 8 sorted partials ----
    if (j < 16) {
        u64 key[16];
        #pragma unroll
        for (int p = 0; p < 16; p++) key[p] = ~0ull;
        for (int seg = 0; seg < 8; seg++) {
            const u64* L = sPart + (size_t)(j * 8 + seg) * 16;
            #pragma unroll
            for (int q = 0; q < 16; q++) {
                u64 a = L[q];
                if (a >= key[15]) break;
                #pragma unroll
                for (int p = 0; p < 16; p++)
                    if (a < key[p]) { u64 tmp = key[p]; key[p] = a; a = tmp; }
            }
        }
        #pragma unroll
        for (int p = 0; p < 16; p++) sidx[j][p] = (int)(key[p] & 0xFFFFFFFFull);
        int k = g_k[r0 + j]; sK[j] = k; sKi[j] = 1.f / (float)k;
    }
    __syncthreads();

    for (int r = 0; r < 16; r++) {
        int k = sK[r];
        float s = 0.f;
        for (int t = 0; t < k; t++) s += g_h[(size_t)sidx[r][t] * H_N + j];
        sAgg[r][j] = s * sKi[r];
    }
    __syncthreads();

    float acc[16];
    #pragma unroll
    for (int r = 0; r < 16; r++) acc[r] = 0.f;
    for (int t = 0; t < 256; t++) {
        float w = W_res[(size_t)t * H_N + j];
        #pragma unroll
        for (int r = 0; r < 16; r++) acc[r] = fmaf(sAgg[r][t], w, acc[r]);
    }
    __syncthreads();                       // sPart (=sZ) fully consumed before sZ writes
    #pragma unroll
    for (int r = 0; r < 16; r++) {
        float rv = fmaxf(acc[r] + br, 0.f);
        sZ[r][j] = g_h[(size_t)(r0 + r) * H_N + j] + rv;
    }
    __syncthreads();

    int wid = j >> 5, lane = j & 31;
    for (int rr = 0; rr < 2; rr++) {
        int lr = wid * 2 + rr;
        int row = r0 + lr;
        float zv[8]; float s = 0.f, s2 = 0.f;
        #pragma unroll
        for (int q = 0; q < 8; q++) {
            zv[q] = sZ[lr][lane + q * 32];
            s += zv[q]; s2 = fmaf(zv[q], zv[q], s2);
        }
        #pragma unroll
        for (int o = 16; o > 0; o >>= 1) {
            s  += __shfl_xor_sync(~0u, s,  o);
            s2 += __shfl_xor_sync(~0u, s2, o);
        }
        float mu   = s * (1.f / 256.f);
        float var  = s2 * (1.f / 256.f) - mu * mu;
        float rstd = 1.0f / sqrtf(var + 1e-5f);
        float po[6] = {0, 0, 0, 0, 0, 0};
        #pragma unroll
        for (int q = 0; q < 8; q++) {
            int tcol = lane + q * 32;
            float a = (zv[q] - mu) * rstd * sG[tcol] + sBn[tcol];
            #pragma unroll
            for (int c = 0; c < 6; c++) po[c] = fmaf(a, sWfc[tcol * 6 + c], po[c]);
        }
        #pragma unroll
        for (int c = 0; c < 6; c++) {
            #pragma unroll
            for (int o = 16; o > 0; o >>= 1) po[c] += __shfl_xor_sync(~0u, po[c], o);
        }
        if (lane == 0) {
            #pragma unroll
            for (int c = 0; c < 6; c++) out[(size_t)row * C_N + c] = po[c] + sbfc[c];
        }
    }
}

// ============================================================
extern "C" void kernel_launch(void* const* d_in, const int* in_sizes, int n_in,
                              void* d_out, int out_size) {
    const float* x      = (const float*)d_in[0];
    const float* W_proj = (const float*)d_in[1];
    const float* b_proj = (const float*)d_in[2];
    const float* W_tau  = (const float*)d_in[3];
    const float* b_tau  = (const float*)d_in[4];
    const float* W_res  = (const float*)d_in[5];
    const float* b_res  = (const float*)d_in[6];
    const float* ln_g   = (const float*)d_in[7];
    const float* ln_b   = (const float*)d_in[8];
    const float* W_fc   = (const float*)d_in[9];
    const float* b_fc   = (const float*)d_in[10];
    float* out = (float*)d_out;

    cudaFuncSetAttribute(gemm_kernel, cudaFuncAttributeMaxDynamicSharedMemorySize, KNN_SMEM);

    preppack_kernel<<<B_N + (D_X * H_N) / 128, 128>>>(x, W_tau, b_tau, W_proj);
    gemm_kernel<<<NPAIR + 128, 128, KNN_SMEM>>>(b_proj);
    resln_kernel<<<B_N / 16, 256>>>(W_res, b_res, ln_g, ln_b, W_fc, b_fc, out);
}